// round 9
// baseline (speedup 1.0000x reference)
#include <cuda_runtime.h>
#include <cuda_bf16.h>
#include <cstdint>

// Problem constants
#define B_    128
#define Q_    30
#define D_    200
#define E_    300
#define C_    128
#define QROWS 3840
#define DROWS 25600
#define NROWS 29440          // 230 * 128
#define NCOLS 768
#define KP    320            // padded K per split-pass

typedef unsigned long long u64;

// ================= f32x2 / misc helpers =================
__device__ __forceinline__ u64 dupf(float x) {
    u64 r; unsigned xi = __float_as_uint(x);
    asm("mov.b64 %0, {%1, %1};" : "=l"(r) : "r"(xi));
    return r;
}
__device__ __forceinline__ u64 packf(float lo, float hi) {
    u64 r; unsigned a = __float_as_uint(lo), b = __float_as_uint(hi);
    asm("mov.b64 %0, {%1, %2};" : "=l"(r) : "r"(a), "r"(b));
    return r;
}
__device__ __forceinline__ void unpackf(u64 v, float& lo, float& hi) {
    unsigned a, b;
    asm("mov.b64 {%0, %1}, %2;" : "=r"(a), "=r"(b) : "l"(v));
    lo = __uint_as_float(a); hi = __uint_as_float(b);
}
__device__ __forceinline__ void ffma2(u64& d, u64 a, u64 b) {
    asm("fma.rn.f32x2 %0, %1, %2, %0;" : "+l"(d) : "l"(a), "l"(b));
}
__device__ __forceinline__ u64 add2(u64 a, u64 b) {
    u64 r; asm("add.rn.f32x2 %0, %1, %2;" : "=l"(r) : "l"(a), "l"(b)); return r;
}
__device__ __forceinline__ u64 mul2(u64 a, u64 b) {
    u64 r; asm("mul.rn.f32x2 %0, %1, %2;" : "=l"(r) : "l"(a), "l"(b)); return r;
}
__device__ __forceinline__ float ex2f(float x) {
    float r; asm("ex2.approx.f32 %0, %1;" : "=f"(r) : "f"(x)); return r;
}
__device__ __forceinline__ void cpasync16(uint32_t sdst, const void* gsrc) {
    asm volatile("cp.async.cg.shared.global [%0], [%1], 16;" :: "r"(sdst), "l"(gsrc));
}
__device__ __forceinline__ void cpasync16z(uint32_t sdst, const void* gsrc, int sz) {
    asm volatile("cp.async.cg.shared.global [%0], [%1], 16, %2;" :: "r"(sdst), "l"(gsrc), "r"(sz));
}
__device__ __forceinline__ uint32_t smem_u32(const void* p) {
    uint32_t a;
    asm("{ .reg .u64 t; cvta.to.shared.u64 t, %1; cvt.u32.u64 %0, t; }" : "=r"(a) : "l"(p));
    return a;
}
__device__ __forceinline__ void ldmatrix_x4(uint32_t* r, uint32_t saddr) {
    asm volatile("ldmatrix.sync.aligned.m8n8.x4.shared.b16 {%0,%1,%2,%3}, [%4];"
                 : "=r"(r[0]), "=r"(r[1]), "=r"(r[2]), "=r"(r[3]) : "r"(saddr));
}
__device__ __forceinline__ void mma_bf16(float* c, const uint32_t* a,
                                         uint32_t b0, uint32_t b1) {
    asm volatile("mma.sync.aligned.m16n8k16.row.col.f32.bf16.bf16.f32 "
                 "{%0,%1,%2,%3}, {%4,%5,%6,%7}, {%8,%9}, {%0,%1,%2,%3};"
                 : "+f"(c[0]), "+f"(c[1]), "+f"(c[2]), "+f"(c[3])
                 : "r"(a[0]), "r"(a[1]), "r"(a[2]), "r"(a[3]), "r"(b0), "r"(b1));
}

// ================= device scratch =================
__device__ __nv_bfloat16 g_Ahi[(size_t)NROWS * KP];
__device__ __nv_bfloat16 g_Alo[(size_t)NROWS * KP];
__device__ __nv_bfloat16 g_Whi[(size_t)NCOLS * KP];
__device__ __nv_bfloat16 g_Wlo[(size_t)NCOLS * KP];
__device__ float g_P[(size_t)NROWS * NCOLS];
__device__ __nv_bfloat16 g_qnh[3 * (size_t)QROWS * C_];
__device__ __nv_bfloat16 g_qnl[3 * (size_t)QROWS * C_];
__device__ __nv_bfloat16 g_dnh[3 * (size_t)DROWS * C_];
__device__ __nv_bfloat16 g_dnl[3 * (size_t)DROWS * C_];
__device__ float g_feats[B_ * 99];

// ================= pack kernel (W + A merged) =================
#define WBLOCKS ((NCOLS * KP + 255) / 256)
#define ABLOCKS ((NROWS * (KP / 4) + 255) / 256)
__global__ void pack_all(const float* __restrict__ w1,
                         const float* __restrict__ w2,
                         const float* __restrict__ w3,
                         const float* __restrict__ emb,
                         const int* __restrict__ qtok,
                         const int* __restrict__ dtok)
{
    if (blockIdx.x < WBLOCKS) {
        int idx = blockIdx.x * 256 + threadIdx.x;
        if (idx >= NCOLS * KP) return;
        int n = idx / KP, k = idx % KP;
        float v = 0.f;
        if (k < E_) {
            if (n < 128)       v = w1[n * E_ + k];
            else if (n < 384) { int u = n - 128; v = w2[(u & 127) * (E_ * 2) + k * 2 + (u >> 7)]; }
            else              { int u = n - 384; v = w3[(u & 127) * (E_ * 3) + k * 3 + (u >> 7)]; }
        }
        __nv_bfloat16 h = __float2bfloat16(v);
        __nv_bfloat16 l = __float2bfloat16(v - __bfloat162float(h));
        g_Whi[idx] = h; g_Wlo[idx] = l;
    } else {
        int idx = (blockIdx.x - WBLOCKS) * 256 + threadIdx.x;
        if (idx >= NROWS * (KP / 4)) return;
        int r = idx / (KP / 4), g = idx % (KP / 4);
        int k = g * 4;
        float4 v = make_float4(0.f, 0.f, 0.f, 0.f);
        if (k < E_) {
            int tok = (r < QROWS) ? qtok[r] : dtok[r - QROWS];
            v = *(const float4*)(emb + (size_t)tok * E_ + k);
        }
        float vv[4] = {v.x, v.y, v.z, v.w};
        u64 hw = 0, lw = 0;
#pragma unroll
        for (int i = 0; i < 4; i++) {
            __nv_bfloat16 h = __float2bfloat16(vv[i]);
            __nv_bfloat16 l = __float2bfloat16(vv[i] - __bfloat162float(h));
            hw |= (u64)(*(unsigned short*)&h) << (16 * i);
            lw |= (u64)(*(unsigned short*)&l) << (16 * i);
        }
        *(u64*)(g_Ahi + (size_t)r * KP + k) = hw;
        *(u64*)(g_Alo + (size_t)r * KP + k) = lw;
    }
}

// ================= K1: HMMA GEMM  P = A' @ W'^T  (bf16 split, K'=960) =================
// CTA tile 128x256, 16 warps (4x4), warp tile 32x64, KC=32, 3-stage cp.async.
#define KC        32
#define NCHUNK    30
#define A_BYTES   (128 * 64)
#define B_BYTES   (256 * 64)
#define STAGE_B   (A_BYTES + B_BYTES)
#define K1_SMEM   (3 * STAGE_B)

__device__ __forceinline__ uint32_t swz(int row, int ch) {
    return (uint32_t)(row * 64 + ((ch ^ ((row >> 1) & 3)) << 4));
}

__global__ __launch_bounds__(512, 1) void k1h()
{
    extern __shared__ char smem[];
    const uint32_t sb = smem_u32(smem);
    const int tid = threadIdx.x;
    const int lane = tid & 31;
    const int wid = tid >> 5;
    const int warp_m = wid & 3;        // 0..3 (32 rows each)
    const int warp_n = wid >> 2;       // 0..3 (64 cols each)
    const int bm0 = blockIdx.x * 128;
    const int bn0 = blockIdx.y * 256;

    float c[2][8][4];
#pragma unroll
    for (int i = 0; i < 2; i++)
#pragma unroll
        for (int j = 0; j < 8; j++)
#pragma unroll
            for (int k = 0; k < 4; k++) c[i][j][k] = 0.f;

    auto load_stage = [&](int chunk, int st) {
        const int pass = chunk / 10;
        const int kloc = (chunk % 10) * KC;
        const __nv_bfloat16* As = (pass == 2) ? g_Alo : g_Ahi;
        const __nv_bfloat16* Bs = (pass == 1) ? g_Wlo : g_Whi;
        const uint32_t aB = sb + st * STAGE_B;
        const uint32_t bB = aB + A_BYTES;
        {
            int row = tid >> 2, ch = tid & 3;      // A: 128 rows x 4 chunks = 512 units
            cpasync16(aB + swz(row, ch), As + (size_t)(bm0 + row) * KP + kloc + ch * 8);
        }
#pragma unroll
        for (int j = 0; j < 2; j++) {
            int u = tid + j * 512;                 // B: 256 rows x 4 chunks = 1024 units
            int row = u >> 2, ch = u & 3;
            cpasync16(bB + swz(row, ch), Bs + (size_t)(bn0 + row) * KP + kloc + ch * 8);
        }
        asm volatile("cp.async.commit_group;");
    };

    load_stage(0, 0);
    load_stage(1, 1);

    const int rit = (lane & 7) + ((lane >> 3) & 1) * 8;

    for (int cidx = 0; cidx < NCHUNK; cidx++) {
        const int st = cidx % 3;
        if (cidx < NCHUNK - 1) asm volatile("cp.async.wait_group 1;");
        else                   asm volatile("cp.async.wait_group 0;");
        __syncthreads();
        if (cidx + 2 < NCHUNK) load_stage(cidx + 2, (cidx + 2) % 3);

        const uint32_t aB = sb + st * STAGE_B;
        const uint32_t bB = aB + A_BYTES;
#pragma unroll
        for (int ks = 0; ks < 2; ks++) {
            const int kch = ks * 2 + (lane >> 4);
            uint32_t a[2][4], b[4][4];
#pragma unroll
            for (int mi = 0; mi < 2; mi++) {
                int r = warp_m * 32 + mi * 16 + rit;
                ldmatrix_x4(a[mi], aB + swz(r, kch));
            }
#pragma unroll
            for (int nj = 0; nj < 4; nj++) {
                int r = warp_n * 64 + nj * 16 + rit;
                ldmatrix_x4(b[nj], bB + swz(r, kch));
            }
#pragma unroll
            for (int mi = 0; mi < 2; mi++)
#pragma unroll
                for (int nj = 0; nj < 4; nj++) {
                    mma_bf16(c[mi][2 * nj],     a[mi], b[nj][0], b[nj][2]);
                    mma_bf16(c[mi][2 * nj + 1], a[mi], b[nj][1], b[nj][3]);
                }
        }
        __syncthreads();
    }

#pragma unroll
    for (int mi = 0; mi < 2; mi++) {
        const int r0 = bm0 + warp_m * 32 + mi * 16 + (lane >> 2);
#pragma unroll
        for (int nj = 0; nj < 4; nj++) {
#pragma unroll
            for (int h = 0; h < 2; h++) {
                const float* cc = c[mi][2 * nj + h];
                const int col = bn0 + warp_n * 64 + nj * 16 + h * 8 + (lane & 3) * 2;
                *(float2*)&g_P[(size_t)r0 * NCOLS + col]       = make_float2(cc[0], cc[1]);
                *(float2*)&g_P[(size_t)(r0 + 8) * NCOLS + col] = make_float2(cc[2], cc[3]);
            }
        }
    }
}

// ================= K2: tap-combine + bias + ReLU + L2-normalize (bf16 split out) =====
__global__ void k2_combine(const float* __restrict__ cb1,
                           const float* __restrict__ cb2,
                           const float* __restrict__ cb3)
{
    const int r = blockIdx.x;
    const int c = threadIdx.x;
    int l, L, rr;
    const bool isq = (r < QROWS);
    if (isq) { rr = r;          l = r % Q_;  L = Q_; }
    else     { rr = r - QROWS;  l = rr % D_; L = D_; }

    const float* Pr = g_P + (size_t)r * NCOLS;
    float v1 = cb1[c] + Pr[c];
    float v2 = cb2[c] + Pr[128 + c];
    float v3 = cb3[c] + Pr[384 + c];
    if (l + 1 < L) { v2 += Pr[NCOLS + 256 + c]; v3 += Pr[NCOLS + 512 + c]; }
    if (l + 2 < L) { v3 += Pr[2 * NCOLS + 640 + c]; }
    v1 = fmaxf(v1, 0.f); v2 = fmaxf(v2, 0.f); v3 = fmaxf(v3, 0.f);

    float s1 = v1 * v1, s2 = v2 * v2, s3 = v3 * v3;
#pragma unroll
    for (int o = 16; o; o >>= 1) {
        s1 += __shfl_xor_sync(0xffffffffu, s1, o);
        s2 += __shfl_xor_sync(0xffffffffu, s2, o);
        s3 += __shfl_xor_sync(0xffffffffu, s3, o);
    }
    __shared__ float sred[3][4];
    const int lane = c & 31, w = c >> 5;
    if (lane == 0) { sred[0][w] = s1; sred[1][w] = s2; sred[2][w] = s3; }
    __syncthreads();
    float ss1 = sred[0][0] + sred[0][1] + sred[0][2] + sred[0][3];
    float ss2 = sred[1][0] + sred[1][1] + sred[1][2] + sred[1][3];
    float ss3 = sred[2][0] + sred[2][1] + sred[2][2] + sred[2][3];
    float n1 = v1 * (1.0f / (sqrtf(ss1) + 1e-13f));
    float n2 = v2 * (1.0f / (sqrtf(ss2) + 1e-13f));
    float n3 = v3 * (1.0f / (sqrtf(ss3) + 1e-13f));

    float nv[3] = {n1, n2, n3};
#pragma unroll
    for (int t = 0; t < 3; t++) {
        __nv_bfloat16 h = __float2bfloat16(nv[t]);
        __nv_bfloat16 lo = __float2bfloat16(nv[t] - __bfloat162float(h));
        if (isq) {
            size_t o = ((size_t)t * QROWS + rr) * C_ + c;
            g_qnh[o] = h; g_qnl[o] = lo;
        } else {
            size_t o = ((size_t)t * DROWS + rr) * C_ + c;
            g_dnh[o] = h; g_dnl[o] = lo;
        }
    }
}

// ================= K3: HMMA cosine GEMM + chain-RBF + log pooling =================
#define K3Q_HI   0
#define K3Q_LO   8192
#define K3D      16384
#define K3SPK    81920
#define K3QM     83328
#define K3DM     83456
#define K3_SMEM  84480

__global__ __launch_bounds__(512, 1) void k3h(const int* __restrict__ qtok,
                                              const int* __restrict__ dtok)
{
    extern __shared__ char smem[];
    const uint32_t sb = smem_u32(smem);
    float* spk = (float*)(smem + K3SPK);
    float* qm  = (float*)(smem + K3QM);
    float* dm  = (float*)(smem + K3DM);

    const int b = blockIdx.x, pair = blockIdx.y;
    const int qi3 = pair / 3, dj3 = pair % 3;
    const int tid = threadIdx.x, lane = tid & 31, wid = tid >> 5;
    const int mi = wid >> 3, wn = wid & 7;

    if (tid < 352) spk[tid] = 0.f;
    if (tid < 32) qm[tid] = (tid < Q_ && qtok[b * Q_ + tid] > 0) ? 1.f : 0.f;
    else if (tid < 288) { int d = tid - 32; dm[d] = (d < D_ && dtok[b * D_ + d] > 0) ? 1.f : 0.f; }

    const __nv_bfloat16* qh = g_qnh + ((size_t)qi3 * QROWS + b * Q_) * C_;
    const __nv_bfloat16* qlp = g_qnl + ((size_t)qi3 * QROWS + b * Q_) * C_;
    const __nv_bfloat16* dh = g_dnh + ((size_t)dj3 * DROWS + b * D_) * C_;
    const __nv_bfloat16* dl = g_dnl + ((size_t)dj3 * DROWS + b * D_) * C_;

    {
        int kc = tid >> 7, row = (tid >> 2) & 31, ch = tid & 3;
        int sz = (row < Q_) ? 16 : 0;
        int srow = (row < Q_) ? row : 0;
        size_t so = (size_t)srow * C_ + kc * 32 + ch * 8;
        uint32_t dst = sb + kc * 2048 + swz(row, ch);
        cpasync16z(dst,          qh  + so, sz);
        cpasync16z(dst + K3Q_LO, qlp + so, sz);
    }

    auto load_d = [&](int kc, int buf) {
#pragma unroll
        for (int j = 0; j < 2; j++) {
            int u = tid + j * 512;
            int row = u >> 2, ch = u & 3;
            int sz = (row < D_) ? 16 : 0;
            int srow = (row < D_) ? row : 0;
            size_t so = (size_t)srow * C_ + kc * 32 + ch * 8;
            uint32_t dst = sb + K3D + buf * 32768 + swz(row, ch);
            cpasync16z(dst,          dh + so, sz);
            cpasync16z(dst + 16384,  dl + so, sz);
        }
        asm volatile("cp.async.commit_group;");
    };

    load_d(0, 0);

    float c[4][4];
#pragma unroll
    for (int i = 0; i < 4; i++)
#pragma unroll
        for (int j = 0; j < 4; j++) c[i][j] = 0.f;

    const int rit = (lane & 7) + ((lane >> 3) & 1) * 8;

    for (int kc = 0; kc < 4; kc++) {
        if (kc < 3) load_d(kc + 1, (kc + 1) & 1);
        if (kc < 3) asm volatile("cp.async.wait_group 1;");
        else        asm volatile("cp.async.wait_group 0;");
        __syncthreads();
        const uint32_t dbB = sb + K3D + (kc & 1) * 32768;
#pragma unroll
        for (int pass = 0; pass < 3; pass++) {
            const uint32_t qB = sb + ((pass == 2) ? K3Q_LO : K3Q_HI) + kc * 2048;
            const uint32_t dB = dbB + ((pass == 1) ? 16384 : 0);
#pragma unroll
            for (int ks = 0; ks < 2; ks++) {
                int kch = ks * 2 + (lane >> 4);
                uint32_t a[4], b0[4], b1[4];
                ldmatrix_x4(a,  qB + swz(mi * 16 + rit, kch));
                ldmatrix_x4(b0, dB + swz(wn * 32 + rit, kch));
                ldmatrix_x4(b1, dB + swz(wn * 32 + 16 + rit, kch));
                mma_bf16(c[0], a, b0[0], b0[2]);
                mma_bf16(c[1], a, b0[1], b0[3]);
                mma_bf16(c[2], a, b1[0], b1[2]);
                mma_bf16(c[3], a, b1[1], b1[3]);
            }
        }
        __syncthreads();
    }

    const float K20 = 28.853901f;
    const float AW  = -72.134754f;
    const float A0  = -7.2134754e8f;
    const u64 C4  = dupf(1.8315639e-2f);
    const u64 C8  = dupf(3.3546262e-4f);
    const u64 C12 = dupf(6.1442124e-6f);
    const u64 C16 = dupf(1.1253517e-7f);

#pragma unroll
    for (int s = 0; s < 2; s++) {
        const int row = mi * 16 + (lane >> 2) + s * 8;
        const float qmr = qm[row];
        float pk0 = 0.f;
        u64 pk56 = 0, pk47 = 0, pk38 = 0, pk29 = 0, pk110 = 0;
#pragma unroll
        for (int nj = 0; nj < 4; nj++) {
#pragma unroll
            for (int h = 0; h < 2; h++) {
                float v = c[nj][2 * s + h];
                int col = wn * 32 + nj * 8 + (lane & 3) * 2 + h;
                float m = qmr * dm[col];
                float cm = v * m;
                float arg = cm * K20;
                float t  = ex2f(arg);
                float ti = ex2f(-arg);
                u64 tt = packf(t, ti);
                float dlt = cm - 0.1f;
                float gl = ex2f(dlt * dlt * AW);
                u64 ab = packf(gl, gl * ti);
                u64 m2 = dupf(m);
                ffma2(pk56, m2, ab);
                ab = mul2(ab, tt); ab = mul2(ab, C4);  ffma2(pk47, m2, ab);
                ab = mul2(ab, tt); ab = mul2(ab, C8);  ffma2(pk38, m2, ab);
                ab = mul2(ab, tt); ab = mul2(ab, C12); ffma2(pk29, m2, ab);
                ab = mul2(ab, tt); ab = mul2(ab, C16); ffma2(pk110, m2, ab);
                float d1 = cm - 1.f;
                pk0 = fmaf(m, ex2f(d1 * d1 * A0), pk0);
            }
        }
#pragma unroll
        for (int o = 1; o <= 2; o <<= 1) {
            pk0  += __shfl_xor_sync(0xffffffffu, pk0, o);
            pk56  = add2(pk56,  __shfl_xor_sync(0xffffffffu, pk56, o));
            pk47  = add2(pk47,  __shfl_xor_sync(0xffffffffu, pk47, o));
            pk38  = add2(pk38,  __shfl_xor_sync(0xffffffffu, pk38, o));
            pk29  = add2(pk29,  __shfl_xor_sync(0xffffffffu, pk29, o));
            pk110 = add2(pk110, __shfl_xor_sync(0xffffffffu, pk110, o));
        }
        if ((lane & 3) == 0) {
            float lo, hi;
            float* rw = spk + row * 11;
            atomicAdd(&rw[0], pk0);
            unpackf(pk56,  lo, hi); atomicAdd(&rw[5], lo); atomicAdd(&rw[6],  hi);
            unpackf(pk47,  lo, hi); atomicAdd(&rw[4], lo); atomicAdd(&rw[7],  hi);
            unpackf(pk38,  lo, hi); atomicAdd(&rw[3], lo); atomicAdd(&rw[8],  hi);
            unpackf(pk29,  lo, hi); atomicAdd(&rw[2], lo); atomicAdd(&rw[9],  hi);
            unpackf(pk110, lo, hi); atomicAdd(&rw[1], lo); atomicAdd(&rw[10], hi);
        }
    }
    __syncthreads();

    if (tid < 11) {
        float f = 0.f;
        for (int q = 0; q < Q_; q++)
            f += logf(fmaxf(spk[q * 11 + tid], 1e-10f)) * 0.01f * qm[q];
        g_feats[(b * 9 + pair) * 11 + tid] = f;
    }
}

// ================= K4: final dense =================
__global__ void k4_out(const float* __restrict__ dw, float* __restrict__ out)
{
    int b = threadIdx.x;
    float f = 0.f;
#pragma unroll
    for (int j = 0; j < 99; j++) f += g_feats[b * 99 + j] * dw[j];
    out[b] = f;
}

// ================= launch =================
extern "C" void kernel_launch(void* const* d_in, const int* in_sizes, int n_in,
                              void* d_out, int out_size)
{
    (void)in_sizes; (void)n_in; (void)out_size;
    const int*   qtok = (const int*)d_in[0];
    const int*   dtok = (const int*)d_in[1];
    const float* emb  = (const float*)d_in[2];
    const float* w1   = (const float*)d_in[3];
    const float* w2   = (const float*)d_in[4];
    const float* w3   = (const float*)d_in[5];
    const float* cb1  = (const float*)d_in[6];
    const float* cb2  = (const float*)d_in[7];
    const float* cb3  = (const float*)d_in[8];
    const float* dw   = (const float*)d_in[9];
    float* out = (float*)d_out;

    cudaFuncSetAttribute(k1h, cudaFuncAttributeMaxDynamicSharedMemorySize, K1_SMEM);
    cudaFuncSetAttribute(k3h, cudaFuncAttributeMaxDynamicSharedMemorySize, K3_SMEM);

    pack_all<<<WBLOCKS + ABLOCKS, 256>>>(w1, w2, w3, emb, qtok, dtok);
    k1h<<<dim3(230, 3), 512, K1_SMEM>>>();
    k2_combine<<<NROWS, 128>>>(cb1, cb2, cb3);
    k3h<<<dim3(128, 9), 512, K3_SMEM>>>(qtok, dtok);
    k4_out<<<1, 128>>>(dw, out);
}

// round 10
// speedup vs baseline: 1.0840x; 1.0840x over previous
#include <cuda_runtime.h>
#include <cuda_bf16.h>
#include <cstdint>

// Problem constants
#define B_    128
#define Q_    30
#define D_    200
#define E_    300
#define C_    128
#define QROWS 3840
#define DROWS 25600
#define NROWS 29440          // 230 * 128
#define NCOLS 768
#define KP    320            // padded K per split-pass

typedef unsigned long long u64;

// ================= f32x2 / misc helpers =================
__device__ __forceinline__ u64 dupf(float x) {
    u64 r; unsigned xi = __float_as_uint(x);
    asm("mov.b64 %0, {%1, %1};" : "=l"(r) : "r"(xi));
    return r;
}
__device__ __forceinline__ u64 packf(float lo, float hi) {
    u64 r; unsigned a = __float_as_uint(lo), b = __float_as_uint(hi);
    asm("mov.b64 %0, {%1, %2};" : "=l"(r) : "r"(a), "r"(b));
    return r;
}
__device__ __forceinline__ void unpackf(u64 v, float& lo, float& hi) {
    unsigned a, b;
    asm("mov.b64 {%0, %1}, %2;" : "=r"(a), "=r"(b) : "l"(v));
    lo = __uint_as_float(a); hi = __uint_as_float(b);
}
__device__ __forceinline__ void ffma2(u64& d, u64 a, u64 b) {
    asm("fma.rn.f32x2 %0, %1, %2, %0;" : "+l"(d) : "l"(a), "l"(b));
}
__device__ __forceinline__ u64 add2(u64 a, u64 b) {
    u64 r; asm("add.rn.f32x2 %0, %1, %2;" : "=l"(r) : "l"(a), "l"(b)); return r;
}
__device__ __forceinline__ u64 mul2(u64 a, u64 b) {
    u64 r; asm("mul.rn.f32x2 %0, %1, %2;" : "=l"(r) : "l"(a), "l"(b)); return r;
}
__device__ __forceinline__ float ex2f(float x) {
    float r; asm("ex2.approx.f32 %0, %1;" : "=f"(r) : "f"(x)); return r;
}
__device__ __forceinline__ void cpasync16(uint32_t sdst, const void* gsrc) {
    asm volatile("cp.async.cg.shared.global [%0], [%1], 16;" :: "r"(sdst), "l"(gsrc));
}
__device__ __forceinline__ void cpasync16z(uint32_t sdst, const void* gsrc, int sz) {
    asm volatile("cp.async.cg.shared.global [%0], [%1], 16, %2;" :: "r"(sdst), "l"(gsrc), "r"(sz));
}
__device__ __forceinline__ uint32_t smem_u32(const void* p) {
    uint32_t a;
    asm("{ .reg .u64 t; cvta.to.shared.u64 t, %1; cvt.u32.u64 %0, t; }" : "=r"(a) : "l"(p));
    return a;
}
__device__ __forceinline__ void ldmatrix_x4(uint32_t* r, uint32_t saddr) {
    asm volatile("ldmatrix.sync.aligned.m8n8.x4.shared.b16 {%0,%1,%2,%3}, [%4];"
                 : "=r"(r[0]), "=r"(r[1]), "=r"(r[2]), "=r"(r[3]) : "r"(saddr));
}
__device__ __forceinline__ void mma_bf16(float* c, const uint32_t* a,
                                         uint32_t b0, uint32_t b1) {
    asm volatile("mma.sync.aligned.m16n8k16.row.col.f32.bf16.bf16.f32 "
                 "{%0,%1,%2,%3}, {%4,%5,%6,%7}, {%8,%9}, {%0,%1,%2,%3};"
                 : "+f"(c[0]), "+f"(c[1]), "+f"(c[2]), "+f"(c[3])
                 : "r"(a[0]), "r"(a[1]), "r"(a[2]), "r"(a[3]), "r"(b0), "r"(b1));
}

// ================= device scratch =================
__device__ __nv_bfloat16 g_Ahi[(size_t)NROWS * KP];
__device__ __nv_bfloat16 g_Alo[(size_t)NROWS * KP];
__device__ __nv_bfloat16 g_Whi[(size_t)NCOLS * KP];
__device__ __nv_bfloat16 g_Wlo[(size_t)NCOLS * KP];
__device__ float g_P[(size_t)NROWS * NCOLS];
__device__ __nv_bfloat16 g_qnh[3 * (size_t)QROWS * C_];
__device__ __nv_bfloat16 g_qnl[3 * (size_t)QROWS * C_];
__device__ __nv_bfloat16 g_dnh[3 * (size_t)DROWS * C_];
__device__ __nv_bfloat16 g_dnl[3 * (size_t)DROWS * C_];
__device__ float g_feats[B_ * 99];

// ================= pack kernel (W + A merged) =================
#define WBLOCKS ((NCOLS * KP + 255) / 256)
#define ABLOCKS ((NROWS * (KP / 4) + 255) / 256)
__global__ void pack_all(const float* __restrict__ w1,
                         const float* __restrict__ w2,
                         const float* __restrict__ w3,
                         const float* __restrict__ emb,
                         const int* __restrict__ qtok,
                         const int* __restrict__ dtok)
{
    if (blockIdx.x < WBLOCKS) {
        int idx = blockIdx.x * 256 + threadIdx.x;
        if (idx >= NCOLS * KP) return;
        int n = idx / KP, k = idx % KP;
        float v = 0.f;
        if (k < E_) {
            if (n < 128)       v = w1[n * E_ + k];
            else if (n < 384) { int u = n - 128; v = w2[(u & 127) * (E_ * 2) + k * 2 + (u >> 7)]; }
            else              { int u = n - 384; v = w3[(u & 127) * (E_ * 3) + k * 3 + (u >> 7)]; }
        }
        __nv_bfloat16 h = __float2bfloat16(v);
        __nv_bfloat16 l = __float2bfloat16(v - __bfloat162float(h));
        g_Whi[idx] = h; g_Wlo[idx] = l;
    } else {
        int idx = (blockIdx.x - WBLOCKS) * 256 + threadIdx.x;
        if (idx >= NROWS * (KP / 4)) return;
        int r = idx / (KP / 4), g = idx % (KP / 4);
        int k = g * 4;
        float4 v = make_float4(0.f, 0.f, 0.f, 0.f);
        if (k < E_) {
            int tok = (r < QROWS) ? qtok[r] : dtok[r - QROWS];
            v = *(const float4*)(emb + (size_t)tok * E_ + k);
        }
        float vv[4] = {v.x, v.y, v.z, v.w};
        u64 hw = 0, lw = 0;
#pragma unroll
        for (int i = 0; i < 4; i++) {
            __nv_bfloat16 h = __float2bfloat16(vv[i]);
            __nv_bfloat16 l = __float2bfloat16(vv[i] - __bfloat162float(h));
            hw |= (u64)(*(unsigned short*)&h) << (16 * i);
            lw |= (u64)(*(unsigned short*)&l) << (16 * i);
        }
        *(u64*)(g_Ahi + (size_t)r * KP + k) = hw;
        *(u64*)(g_Alo + (size_t)r * KP + k) = lw;
    }
}

// ================= K1: HMMA GEMM  P = A' @ W'^T  (bf16 split, K'=960) =================
// CTA tile 128x256, 16 warps (4x4), warp tile 32x64, KC=64, 3-stage cp.async,
// ONE __syncthreads per chunk (3-stage ring makes the tail barrier redundant).
#define KC        64
#define NCHUNK    15
#define A_BYTES   (128 * 128)      // 128 rows * 128B (64 bf16)
#define B_BYTES   (256 * 128)
#define STAGE_B   (A_BYTES + B_BYTES)
#define K1_SMEM   (3 * STAGE_B)    // 147456

// full SW128 swizzle: 128B rows, 8 x 16B slots, slot ^= (row & 7)
__device__ __forceinline__ uint32_t swz128(int row, int ch) {
    return (uint32_t)(row * 128 + ((ch ^ (row & 7)) << 4));
}
// 64B-row swizzle for k3h tiles (unchanged from R8)
__device__ __forceinline__ uint32_t swz(int row, int ch) {
    return (uint32_t)(row * 64 + ((ch ^ ((row >> 1) & 3)) << 4));
}

__global__ __launch_bounds__(512, 1) void k1h()
{
    extern __shared__ char smem[];
    const uint32_t sb = smem_u32(smem);
    const int tid = threadIdx.x;
    const int lane = tid & 31;
    const int wid = tid >> 5;
    const int warp_m = wid & 3;        // 0..3 (32 rows each)
    const int warp_n = wid >> 2;       // 0..3 (64 cols each)
    const int bm0 = blockIdx.x * 128;
    const int bn0 = blockIdx.y * 256;

    float c[2][8][4];
#pragma unroll
    for (int i = 0; i < 2; i++)
#pragma unroll
        for (int j = 0; j < 8; j++)
#pragma unroll
            for (int k = 0; k < 4; k++) c[i][j][k] = 0.f;

    auto load_stage = [&](int chunk, int st) {
        const int pass = chunk / 5;
        const int kloc = (chunk % 5) * KC;
        const __nv_bfloat16* As = (pass == 2) ? g_Alo : g_Ahi;
        const __nv_bfloat16* Bs = (pass == 1) ? g_Wlo : g_Whi;
        const uint32_t aB = sb + st * STAGE_B;
        const uint32_t bB = aB + A_BYTES;
#pragma unroll
        for (int j = 0; j < 2; j++) {
            int u = tid + j * 512;                 // A: 128 rows x 8 slots = 1024 units
            int row = u >> 3, ch = u & 7;
            cpasync16(aB + swz128(row, ch), As + (size_t)(bm0 + row) * KP + kloc + ch * 8);
        }
#pragma unroll
        for (int j = 0; j < 4; j++) {
            int u = tid + j * 512;                 // B: 256 rows x 8 slots = 2048 units
            int row = u >> 3, ch = u & 7;
            cpasync16(bB + swz128(row, ch), Bs + (size_t)(bn0 + row) * KP + kloc + ch * 8);
        }
        asm volatile("cp.async.commit_group;");
    };

    load_stage(0, 0);
    load_stage(1, 1);

    const int rit = (lane & 7) + ((lane >> 3) & 1) * 8;

    for (int cidx = 0; cidx < NCHUNK; cidx++) {
        const int st = cidx % 3;
        if (cidx < NCHUNK - 1) asm volatile("cp.async.wait_group 1;");
        else                   asm volatile("cp.async.wait_group 0;");
        __syncthreads();                           // single barrier per chunk
        if (cidx + 2 < NCHUNK) load_stage(cidx + 2, (cidx + 2) % 3);

        const uint32_t aB = sb + st * STAGE_B;
        const uint32_t bB = aB + A_BYTES;
#pragma unroll
        for (int ks = 0; ks < 4; ks++) {
            const int kch = ks * 2 + (lane >> 4);
            uint32_t a[2][4], b[4][4];
#pragma unroll
            for (int mi = 0; mi < 2; mi++) {
                int r = warp_m * 32 + mi * 16 + rit;
                ldmatrix_x4(a[mi], aB + swz128(r, kch));
            }
#pragma unroll
            for (int nj = 0; nj < 4; nj++) {
                int r = warp_n * 64 + nj * 16 + rit;
                ldmatrix_x4(b[nj], bB + swz128(r, kch));
            }
#pragma unroll
            for (int mi = 0; mi < 2; mi++)
#pragma unroll
                for (int nj = 0; nj < 4; nj++) {
                    mma_bf16(c[mi][2 * nj],     a[mi], b[nj][0], b[nj][2]);
                    mma_bf16(c[mi][2 * nj + 1], a[mi], b[nj][1], b[nj][3]);
                }
        }
    }

#pragma unroll
    for (int mi = 0; mi < 2; mi++) {
        const int r0 = bm0 + warp_m * 32 + mi * 16 + (lane >> 2);
#pragma unroll
        for (int nj = 0; nj < 4; nj++) {
#pragma unroll
            for (int h = 0; h < 2; h++) {
                const float* cc = c[mi][2 * nj + h];
                const int col = bn0 + warp_n * 64 + nj * 16 + h * 8 + (lane & 3) * 2;
                *(float2*)&g_P[(size_t)r0 * NCOLS + col]       = make_float2(cc[0], cc[1]);
                *(float2*)&g_P[(size_t)(r0 + 8) * NCOLS + col] = make_float2(cc[2], cc[3]);
            }
        }
    }
}

// ================= K2: tap-combine + bias + ReLU + L2-normalize (bf16 split out) =====
__global__ void k2_combine(const float* __restrict__ cb1,
                           const float* __restrict__ cb2,
                           const float* __restrict__ cb3)
{
    const int r = blockIdx.x;
    const int c = threadIdx.x;
    int l, L, rr;
    const bool isq = (r < QROWS);
    if (isq) { rr = r;          l = r % Q_;  L = Q_; }
    else     { rr = r - QROWS;  l = rr % D_; L = D_; }

    const float* Pr = g_P + (size_t)r * NCOLS;
    float v1 = cb1[c] + Pr[c];
    float v2 = cb2[c] + Pr[128 + c];
    float v3 = cb3[c] + Pr[384 + c];
    if (l + 1 < L) { v2 += Pr[NCOLS + 256 + c]; v3 += Pr[NCOLS + 512 + c]; }
    if (l + 2 < L) { v3 += Pr[2 * NCOLS + 640 + c]; }
    v1 = fmaxf(v1, 0.f); v2 = fmaxf(v2, 0.f); v3 = fmaxf(v3, 0.f);

    float s1 = v1 * v1, s2 = v2 * v2, s3 = v3 * v3;
#pragma unroll
    for (int o = 16; o; o >>= 1) {
        s1 += __shfl_xor_sync(0xffffffffu, s1, o);
        s2 += __shfl_xor_sync(0xffffffffu, s2, o);
        s3 += __shfl_xor_sync(0xffffffffu, s3, o);
    }
    __shared__ float sred[3][4];
    const int lane = c & 31, w = c >> 5;
    if (lane == 0) { sred[0][w] = s1; sred[1][w] = s2; sred[2][w] = s3; }
    __syncthreads();
    float ss1 = sred[0][0] + sred[0][1] + sred[0][2] + sred[0][3];
    float ss2 = sred[1][0] + sred[1][1] + sred[1][2] + sred[1][3];
    float ss3 = sred[2][0] + sred[2][1] + sred[2][2] + sred[2][3];
    float n1 = v1 * (1.0f / (sqrtf(ss1) + 1e-13f));
    float n2 = v2 * (1.0f / (sqrtf(ss2) + 1e-13f));
    float n3 = v3 * (1.0f / (sqrtf(ss3) + 1e-13f));

    float nv[3] = {n1, n2, n3};
#pragma unroll
    for (int t = 0; t < 3; t++) {
        __nv_bfloat16 h = __float2bfloat16(nv[t]);
        __nv_bfloat16 lo = __float2bfloat16(nv[t] - __bfloat162float(h));
        if (isq) {
            size_t o = ((size_t)t * QROWS + rr) * C_ + c;
            g_qnh[o] = h; g_qnl[o] = lo;
        } else {
            size_t o = ((size_t)t * DROWS + rr) * C_ + c;
            g_dnh[o] = h; g_dnl[o] = lo;
        }
    }
}

// ================= K3: HMMA cosine GEMM + chain-RBF + log pooling (R8, unchanged) ====
#define K3Q_HI   0
#define K3Q_LO   8192
#define K3D      16384
#define K3SPK    81920
#define K3QM     83328
#define K3DM     83456
#define K3_SMEM  84480

__global__ __launch_bounds__(512, 1) void k3h(const int* __restrict__ qtok,
                                              const int* __restrict__ dtok)
{
    extern __shared__ char smem[];
    const uint32_t sb = smem_u32(smem);
    float* spk = (float*)(smem + K3SPK);
    float* qm  = (float*)(smem + K3QM);
    float* dm  = (float*)(smem + K3DM);

    const int b = blockIdx.x, pair = blockIdx.y;
    const int qi3 = pair / 3, dj3 = pair % 3;
    const int tid = threadIdx.x, lane = tid & 31, wid = tid >> 5;
    const int mi = wid >> 3, wn = wid & 7;

    if (tid < 352) spk[tid] = 0.f;
    if (tid < 32) qm[tid] = (tid < Q_ && qtok[b * Q_ + tid] > 0) ? 1.f : 0.f;
    else if (tid < 288) { int d = tid - 32; dm[d] = (d < D_ && dtok[b * D_ + d] > 0) ? 1.f : 0.f; }

    const __nv_bfloat16* qh = g_qnh + ((size_t)qi3 * QROWS + b * Q_) * C_;
    const __nv_bfloat16* qlp = g_qnl + ((size_t)qi3 * QROWS + b * Q_) * C_;
    const __nv_bfloat16* dh = g_dnh + ((size_t)dj3 * DROWS + b * D_) * C_;
    const __nv_bfloat16* dl = g_dnl + ((size_t)dj3 * DROWS + b * D_) * C_;

    {
        int kc = tid >> 7, row = (tid >> 2) & 31, ch = tid & 3;
        int sz = (row < Q_) ? 16 : 0;
        int srow = (row < Q_) ? row : 0;
        size_t so = (size_t)srow * C_ + kc * 32 + ch * 8;
        uint32_t dst = sb + kc * 2048 + swz(row, ch);
        cpasync16z(dst,          qh  + so, sz);
        cpasync16z(dst + K3Q_LO, qlp + so, sz);
    }

    auto load_d = [&](int kc, int buf) {
#pragma unroll
        for (int j = 0; j < 2; j++) {
            int u = tid + j * 512;
            int row = u >> 2, ch = u & 3;
            int sz = (row < D_) ? 16 : 0;
            int srow = (row < D_) ? row : 0;
            size_t so = (size_t)srow * C_ + kc * 32 + ch * 8;
            uint32_t dst = sb + K3D + buf * 32768 + swz(row, ch);
            cpasync16z(dst,          dh + so, sz);
            cpasync16z(dst + 16384,  dl + so, sz);
        }
        asm volatile("cp.async.commit_group;");
    };

    load_d(0, 0);

    float c[4][4];
#pragma unroll
    for (int i = 0; i < 4; i++)
#pragma unroll
        for (int j = 0; j < 4; j++) c[i][j] = 0.f;

    const int rit = (lane & 7) + ((lane >> 3) & 1) * 8;

    for (int kc = 0; kc < 4; kc++) {
        if (kc < 3) load_d(kc + 1, (kc + 1) & 1);
        if (kc < 3) asm volatile("cp.async.wait_group 1;");
        else        asm volatile("cp.async.wait_group 0;");
        __syncthreads();
        const uint32_t dbB = sb + K3D + (kc & 1) * 32768;
#pragma unroll
        for (int pass = 0; pass < 3; pass++) {
            const uint32_t qB = sb + ((pass == 2) ? K3Q_LO : K3Q_HI) + kc * 2048;
            const uint32_t dB = dbB + ((pass == 1) ? 16384 : 0);
#pragma unroll
            for (int ks = 0; ks < 2; ks++) {
                int kch = ks * 2 + (lane >> 4);
                uint32_t a[4], b0[4], b1[4];
                ldmatrix_x4(a,  qB + swz(mi * 16 + rit, kch));
                ldmatrix_x4(b0, dB + swz(wn * 32 + rit, kch));
                ldmatrix_x4(b1, dB + swz(wn * 32 + 16 + rit, kch));
                mma_bf16(c[0], a, b0[0], b0[2]);
                mma_bf16(c[1], a, b0[1], b0[3]);
                mma_bf16(c[2], a, b1[0], b1[2]);
                mma_bf16(c[3], a, b1[1], b1[3]);
            }
        }
        __syncthreads();
    }

    const float K20 = 28.853901f;
    const float AW  = -72.134754f;
    const float A0  = -7.2134754e8f;
    const u64 C4  = dupf(1.8315639e-2f);
    const u64 C8  = dupf(3.3546262e-4f);
    const u64 C12 = dupf(6.1442124e-6f);
    const u64 C16 = dupf(1.1253517e-7f);

#pragma unroll
    for (int s = 0; s < 2; s++) {
        const int row = mi * 16 + (lane >> 2) + s * 8;
        const float qmr = qm[row];
        float pk0 = 0.f;
        u64 pk56 = 0, pk47 = 0, pk38 = 0, pk29 = 0, pk110 = 0;
#pragma unroll
        for (int nj = 0; nj < 4; nj++) {
#pragma unroll
            for (int h = 0; h < 2; h++) {
                float v = c[nj][2 * s + h];
                int col = wn * 32 + nj * 8 + (lane & 3) * 2 + h;
                float m = qmr * dm[col];
                float cm = v * m;
                float arg = cm * K20;
                float t  = ex2f(arg);
                float ti = ex2f(-arg);
                u64 tt = packf(t, ti);
                float dlt = cm - 0.1f;
                float gl = ex2f(dlt * dlt * AW);
                u64 ab = packf(gl, gl * ti);
                u64 m2 = dupf(m);
                ffma2(pk56, m2, ab);
                ab = mul2(ab, tt); ab = mul2(ab, C4);  ffma2(pk47, m2, ab);
                ab = mul2(ab, tt); ab = mul2(ab, C8);  ffma2(pk38, m2, ab);
                ab = mul2(ab, tt); ab = mul2(ab, C12); ffma2(pk29, m2, ab);
                ab = mul2(ab, tt); ab = mul2(ab, C16); ffma2(pk110, m2, ab);
                float d1 = cm - 1.f;
                pk0 = fmaf(m, ex2f(d1 * d1 * A0), pk0);
            }
        }
#pragma unroll
        for (int o = 1; o <= 2; o <<= 1) {
            pk0  += __shfl_xor_sync(0xffffffffu, pk0, o);
            pk56  = add2(pk56,  __shfl_xor_sync(0xffffffffu, pk56, o));
            pk47  = add2(pk47,  __shfl_xor_sync(0xffffffffu, pk47, o));
            pk38  = add2(pk38,  __shfl_xor_sync(0xffffffffu, pk38, o));
            pk29  = add2(pk29,  __shfl_xor_sync(0xffffffffu, pk29, o));
            pk110 = add2(pk110, __shfl_xor_sync(0xffffffffu, pk110, o));
        }
        if ((lane & 3) == 0) {
            float lo, hi;
            float* rw = spk + row * 11;
            atomicAdd(&rw[0], pk0);
            unpackf(pk56,  lo, hi); atomicAdd(&rw[5], lo); atomicAdd(&rw[6],  hi);
            unpackf(pk47,  lo, hi); atomicAdd(&rw[4], lo); atomicAdd(&rw[7],  hi);
            unpackf(pk38,  lo, hi); atomicAdd(&rw[3], lo); atomicAdd(&rw[8],  hi);
            unpackf(pk29,  lo, hi); atomicAdd(&rw[2], lo); atomicAdd(&rw[9],  hi);
            unpackf(pk110, lo, hi); atomicAdd(&rw[1], lo); atomicAdd(&rw[10], hi);
        }
    }
    __syncthreads();

    if (tid < 11) {
        float f = 0.f;
        for (int q = 0; q < Q_; q++)
            f += logf(fmaxf(spk[q * 11 + tid], 1e-10f)) * 0.01f * qm[q];
        g_feats[(b * 9 + pair) * 11 + tid] = f;
    }
}

// ================= K4: final dense =================
__global__ void k4_out(const float* __restrict__ dw, float* __restrict__ out)
{
    int b = threadIdx.x;
    float f = 0.f;
#pragma unroll
    for (int j = 0; j < 99; j++) f += g_feats[b * 99 + j] * dw[j];
    out[b] = f;
}

// ================= launch =================
extern "C" void kernel_launch(void* const* d_in, const int* in_sizes, int n_in,
                              void* d_out, int out_size)
{
    (void)in_sizes; (void)n_in; (void)out_size;
    const int*   qtok = (const int*)d_in[0];
    const int*   dtok = (const int*)d_in[1];
    const float* emb  = (const float*)d_in[2];
    const float* w1   = (const float*)d_in[3];
    const float* w2   = (const float*)d_in[4];
    const float* w3   = (const float*)d_in[5];
    const float* cb1  = (const float*)d_in[6];
    const float* cb2  = (const float*)d_in[7];
    const float* cb3  = (const float*)d_in[8];
    const float* dw   = (const float*)d_in[9];
    float* out = (float*)d_out;

    cudaFuncSetAttribute(k1h, cudaFuncAttributeMaxDynamicSharedMemorySize, K1_SMEM);
    cudaFuncSetAttribute(k3h, cudaFuncAttributeMaxDynamicSharedMemorySize, K3_SMEM);

    pack_all<<<WBLOCKS + ABLOCKS, 256>>>(w1, w2, w3, emb, qtok, dtok);
    k1h<<<dim3(230, 3), 512, K1_SMEM>>>();
    k2_combine<<<NROWS, 128>>>(cb1, cb2, cb3);
    k3h<<<dim3(128, 9), 512, K3_SMEM>>>(qtok, dtok);
    k4_out<<<1, 128>>>(dw, out);
}

// round 12
// speedup vs baseline: 1.1294x; 1.0418x over previous
#include <cuda_runtime.h>
#include <cuda_bf16.h>
#include <cstdint>

// Problem constants
#define B_    128
#define Q_    30
#define D_    200
#define E_    300
#define C_    128
#define QROWS 3840
#define DROWS 25600
#define NROWS 29440          // 230 * 128
#define NCOLS 768
#define KP    320            // padded K per split-pass

typedef unsigned long long u64;

// ================= f32x2 / misc helpers =================
__device__ __forceinline__ u64 dupf(float x) {
    u64 r; unsigned xi = __float_as_uint(x);
    asm("mov.b64 %0, {%1, %1};" : "=l"(r) : "r"(xi));
    return r;
}
__device__ __forceinline__ u64 packf(float lo, float hi) {
    u64 r; unsigned a = __float_as_uint(lo), b = __float_as_uint(hi);
    asm("mov.b64 %0, {%1, %2};" : "=l"(r) : "r"(a), "r"(b));
    return r;
}
__device__ __forceinline__ void unpackf(u64 v, float& lo, float& hi) {
    unsigned a, b;
    asm("mov.b64 {%0, %1}, %2;" : "=r"(a), "=r"(b) : "l"(v));
    lo = __uint_as_float(a); hi = __uint_as_float(b);
}
__device__ __forceinline__ void ffma2(u64& d, u64 a, u64 b) {
    asm("fma.rn.f32x2 %0, %1, %2, %0;" : "+l"(d) : "l"(a), "l"(b));
}
__device__ __forceinline__ u64 add2(u64 a, u64 b) {
    u64 r; asm("add.rn.f32x2 %0, %1, %2;" : "=l"(r) : "l"(a), "l"(b)); return r;
}
__device__ __forceinline__ u64 mul2(u64 a, u64 b) {
    u64 r; asm("mul.rn.f32x2 %0, %1, %2;" : "=l"(r) : "l"(a), "l"(b)); return r;
}
__device__ __forceinline__ float ex2f(float x) {
    float r; asm("ex2.approx.f32 %0, %1;" : "=f"(r) : "f"(x)); return r;
}
__device__ __forceinline__ void cpasync16(uint32_t sdst, const void* gsrc) {
    asm volatile("cp.async.cg.shared.global [%0], [%1], 16;" :: "r"(sdst), "l"(gsrc));
}
__device__ __forceinline__ void cpasync16z(uint32_t sdst, const void* gsrc, int sz) {
    asm volatile("cp.async.cg.shared.global [%0], [%1], 16, %2;" :: "r"(sdst), "l"(gsrc), "r"(sz));
}
__device__ __forceinline__ uint32_t smem_u32(const void* p) {
    uint32_t a;
    asm("{ .reg .u64 t; cvta.to.shared.u64 t, %1; cvt.u32.u64 %0, t; }" : "=r"(a) : "l"(p));
    return a;
}
__device__ __forceinline__ void ldmatrix_x4(uint32_t* r, uint32_t saddr) {
    asm volatile("ldmatrix.sync.aligned.m8n8.x4.shared.b16 {%0,%1,%2,%3}, [%4];"
                 : "=r"(r[0]), "=r"(r[1]), "=r"(r[2]), "=r"(r[3]) : "r"(saddr));
}
__device__ __forceinline__ void mma_bf16(float* c, const uint32_t* a,
                                         uint32_t b0, uint32_t b1) {
    asm volatile("mma.sync.aligned.m16n8k16.row.col.f32.bf16.bf16.f32 "
                 "{%0,%1,%2,%3}, {%4,%5,%6,%7}, {%8,%9}, {%0,%1,%2,%3};"
                 : "+f"(c[0]), "+f"(c[1]), "+f"(c[2]), "+f"(c[3])
                 : "r"(a[0]), "r"(a[1]), "r"(a[2]), "r"(a[3]), "r"(b0), "r"(b1));
}

// ================= device scratch =================
__device__ __nv_bfloat16 g_Ahi[(size_t)NROWS * KP];
__device__ __nv_bfloat16 g_Alo[(size_t)NROWS * KP];
__device__ __nv_bfloat16 g_Whi[(size_t)NCOLS * KP];
__device__ __nv_bfloat16 g_Wlo[(size_t)NCOLS * KP];
__device__ float g_P[(size_t)NROWS * NCOLS];
__device__ __nv_bfloat16 g_qnh[3 * (size_t)QROWS * C_];
__device__ __nv_bfloat16 g_qnl[3 * (size_t)QROWS * C_];
__device__ __nv_bfloat16 g_dnh[3 * (size_t)DROWS * C_];
__device__ __nv_bfloat16 g_dnl[3 * (size_t)DROWS * C_];
__device__ float g_feats[B_ * 99];

// ================= pack kernel (W + A merged) =================
#define WBLOCKS ((NCOLS * KP + 255) / 256)
#define ABLOCKS ((NROWS * (KP / 4) + 255) / 256)
__global__ void pack_all(const float* __restrict__ w1,
                         const float* __restrict__ w2,
                         const float* __restrict__ w3,
                         const float* __restrict__ emb,
                         const int* __restrict__ qtok,
                         const int* __restrict__ dtok)
{
    if (blockIdx.x < WBLOCKS) {
        int idx = blockIdx.x * 256 + threadIdx.x;
        if (idx >= NCOLS * KP) return;
        int n = idx / KP, k = idx % KP;
        float v = 0.f;
        if (k < E_) {
            if (n < 128)       v = w1[n * E_ + k];
            else if (n < 384) { int u = n - 128; v = w2[(u & 127) * (E_ * 2) + k * 2 + (u >> 7)]; }
            else              { int u = n - 384; v = w3[(u & 127) * (E_ * 3) + k * 3 + (u >> 7)]; }
        }
        __nv_bfloat16 h = __float2bfloat16(v);
        __nv_bfloat16 l = __float2bfloat16(v - __bfloat162float(h));
        g_Whi[idx] = h; g_Wlo[idx] = l;
    } else {
        int idx = (blockIdx.x - WBLOCKS) * 256 + threadIdx.x;
        if (idx >= NROWS * (KP / 4)) return;
        int r = idx / (KP / 4), g = idx % (KP / 4);
        int k = g * 4;
        float4 v = make_float4(0.f, 0.f, 0.f, 0.f);
        if (k < E_) {
            int tok = (r < QROWS) ? qtok[r] : dtok[r - QROWS];
            v = *(const float4*)(emb + (size_t)tok * E_ + k);
        }
        float vv[4] = {v.x, v.y, v.z, v.w};
        u64 hw = 0, lw = 0;
#pragma unroll
        for (int i = 0; i < 4; i++) {
            __nv_bfloat16 h = __float2bfloat16(vv[i]);
            __nv_bfloat16 l = __float2bfloat16(vv[i] - __bfloat162float(h));
            hw |= (u64)(*(unsigned short*)&h) << (16 * i);
            lw |= (u64)(*(unsigned short*)&l) << (16 * i);
        }
        *(u64*)(g_Ahi + (size_t)r * KP + k) = hw;
        *(u64*)(g_Alo + (size_t)r * KP + k) = lw;
    }
}

// ================= K1: HMMA GEMM  P = A' @ W'^T  (bf16 split, K'=960) =================
// CTA tile 128x256, 16 warps (4x4), warp tile 32x64, KC=64, 4-stage cp.async ring.
// Per chunk: issue load(c+2) -> wait_group 2 (own copies for chunk c) -> barrier -> compute(c).
// Wait precedes the barrier (cp.async visibility rule); 4 stages make load(c+2)'s target
// stage safe (last read at compute(c-2), separated by iteration c-1's barrier).
#define KC        64
#define NCHUNK    15
#define A_BYTES   (128 * 128)      // 128 rows * 128B (64 bf16)
#define B_BYTES   (256 * 128)
#define STAGE_B   (A_BYTES + B_BYTES)
#define K1_SMEM   (4 * STAGE_B)    // 196608

// full SW128 swizzle: 128B rows, 8 x 16B slots, slot ^= (row & 7)
__device__ __forceinline__ uint32_t swz128(int row, int ch) {
    return (uint32_t)(row * 128 + ((ch ^ (row & 7)) << 4));
}
// 64B-row swizzle for k3h tiles
__device__ __forceinline__ uint32_t swz(int row, int ch) {
    return (uint32_t)(row * 64 + ((ch ^ ((row >> 1) & 3)) << 4));
}

__global__ __launch_bounds__(512, 1) void k1h()
{
    extern __shared__ char smem[];
    const uint32_t sb = smem_u32(smem);
    const int tid = threadIdx.x;
    const int lane = tid & 31;
    const int wid = tid >> 5;
    const int warp_m = wid & 3;        // 0..3 (32 rows each)
    const int warp_n = wid >> 2;       // 0..3 (64 cols each)
    const int bm0 = blockIdx.x * 128;
    const int bn0 = blockIdx.y * 256;

    float c[2][8][4];
#pragma unroll
    for (int i = 0; i < 2; i++)
#pragma unroll
        for (int j = 0; j < 8; j++)
#pragma unroll
            for (int k = 0; k < 4; k++) c[i][j][k] = 0.f;

    auto load_stage = [&](int chunk, int st) {
        const int pass = chunk / 5;
        const int kloc = (chunk % 5) * KC;
        const __nv_bfloat16* As = (pass == 2) ? g_Alo : g_Ahi;
        const __nv_bfloat16* Bs = (pass == 1) ? g_Wlo : g_Whi;
        const uint32_t aB = sb + st * STAGE_B;
        const uint32_t bB = aB + A_BYTES;
#pragma unroll
        for (int j = 0; j < 2; j++) {
            int u = tid + j * 512;                 // A: 128 rows x 8 slots = 1024 units
            int row = u >> 3, ch = u & 7;
            cpasync16(aB + swz128(row, ch), As + (size_t)(bm0 + row) * KP + kloc + ch * 8);
        }
#pragma unroll
        for (int j = 0; j < 4; j++) {
            int u = tid + j * 512;                 // B: 256 rows x 8 slots = 2048 units
            int row = u >> 3, ch = u & 7;
            cpasync16(bB + swz128(row, ch), Bs + (size_t)(bn0 + row) * KP + kloc + ch * 8);
        }
        asm volatile("cp.async.commit_group;");
    };

    load_stage(0, 0);
    load_stage(1, 1);

    const int rit = (lane & 7) + ((lane >> 3) & 1) * 8;

    for (int cidx = 0; cidx < NCHUNK; cidx++) {
        const int st = cidx & 3;
        if (cidx + 2 < NCHUNK) {
            load_stage(cidx + 2, (cidx + 2) & 3);
            asm volatile("cp.async.wait_group 2;");    // chunk c complete (own copies)
        } else if (cidx + 1 < NCHUNK) {
            asm volatile("cp.async.wait_group 1;");
        } else {
            asm volatile("cp.async.wait_group 0;");
        }
        __syncthreads();                               // cross-thread visibility of chunk c

        const uint32_t aB = sb + st * STAGE_B;
        const uint32_t bB = aB + A_BYTES;
#pragma unroll
        for (int ks = 0; ks < 4; ks++) {
            const int kch = ks * 2 + (lane >> 4);
            uint32_t a[2][4], b[4][4];
#pragma unroll
            for (int mi = 0; mi < 2; mi++) {
                int r = warp_m * 32 + mi * 16 + rit;
                ldmatrix_x4(a[mi], aB + swz128(r, kch));
            }
#pragma unroll
            for (int nj = 0; nj < 4; nj++) {
                int r = warp_n * 64 + nj * 16 + rit;
                ldmatrix_x4(b[nj], bB + swz128(r, kch));
            }
#pragma unroll
            for (int mi = 0; mi < 2; mi++)
#pragma unroll
                for (int nj = 0; nj < 4; nj++) {
                    mma_bf16(c[mi][2 * nj],     a[mi], b[nj][0], b[nj][2]);
                    mma_bf16(c[mi][2 * nj + 1], a[mi], b[nj][1], b[nj][3]);
                }
        }
    }

#pragma unroll
    for (int mi = 0; mi < 2; mi++) {
        const int r0 = bm0 + warp_m * 32 + mi * 16 + (lane >> 2);
#pragma unroll
        for (int nj = 0; nj < 4; nj++) {
#pragma unroll
            for (int h = 0; h < 2; h++) {
                const float* cc = c[mi][2 * nj + h];
                const int col = bn0 + warp_n * 64 + nj * 16 + h * 8 + (lane & 3) * 2;
                *(float2*)&g_P[(size_t)r0 * NCOLS + col]       = make_float2(cc[0], cc[1]);
                *(float2*)&g_P[(size_t)(r0 + 8) * NCOLS + col] = make_float2(cc[2], cc[3]);
            }
        }
    }
}

// ================= K2: tap-combine + bias + ReLU + L2-normalize (bf16 split out) =====
__global__ void k2_combine(const float* __restrict__ cb1,
                           const float* __restrict__ cb2,
                           const float* __restrict__ cb3)
{
    const int r = blockIdx.x;
    const int c = threadIdx.x;
    int l, L, rr;
    const bool isq = (r < QROWS);
    if (isq) { rr = r;          l = r % Q_;  L = Q_; }
    else     { rr = r - QROWS;  l = rr % D_; L = D_; }

    const float* Pr = g_P + (size_t)r * NCOLS;
    float v1 = cb1[c] + Pr[c];
    float v2 = cb2[c] + Pr[128 + c];
    float v3 = cb3[c] + Pr[384 + c];
    if (l + 1 < L) { v2 += Pr[NCOLS + 256 + c]; v3 += Pr[NCOLS + 512 + c]; }
    if (l + 2 < L) { v3 += Pr[2 * NCOLS + 640 + c]; }
    v1 = fmaxf(v1, 0.f); v2 = fmaxf(v2, 0.f); v3 = fmaxf(v3, 0.f);

    float s1 = v1 * v1, s2 = v2 * v2, s3 = v3 * v3;
#pragma unroll
    for (int o = 16; o; o >>= 1) {
        s1 += __shfl_xor_sync(0xffffffffu, s1, o);
        s2 += __shfl_xor_sync(0xffffffffu, s2, o);
        s3 += __shfl_xor_sync(0xffffffffu, s3, o);
    }
    __shared__ float sred[3][4];
    const int lane = c & 31, w = c >> 5;
    if (lane == 0) { sred[0][w] = s1; sred[1][w] = s2; sred[2][w] = s3; }
    __syncthreads();
    float ss1 = sred[0][0] + sred[0][1] + sred[0][2] + sred[0][3];
    float ss2 = sred[1][0] + sred[1][1] + sred[1][2] + sred[1][3];
    float ss3 = sred[2][0] + sred[2][1] + sred[2][2] + sred[2][3];
    float n1 = v1 * (1.0f / (sqrtf(ss1) + 1e-13f));
    float n2 = v2 * (1.0f / (sqrtf(ss2) + 1e-13f));
    float n3 = v3 * (1.0f / (sqrtf(ss3) + 1e-13f));

    float nv[3] = {n1, n2, n3};
#pragma unroll
    for (int t = 0; t < 3; t++) {
        __nv_bfloat16 h = __float2bfloat16(nv[t]);
        __nv_bfloat16 lo = __float2bfloat16(nv[t] - __bfloat162float(h));
        if (isq) {
            size_t o = ((size_t)t * QROWS + rr) * C_ + c;
            g_qnh[o] = h; g_qnl[o] = lo;
        } else {
            size_t o = ((size_t)t * DROWS + rr) * C_ + c;
            g_dnh[o] = h; g_dnl[o] = lo;
        }
    }
}

// ================= K3: HMMA cosine GEMM + chain-RBF + log pooling =================
#define K3Q_HI   0
#define K3Q_LO   8192
#define K3D      16384
#define K3SPK    81920
#define K3QM     83328
#define K3DM     83456
#define K3_SMEM  84480

__global__ __launch_bounds__(512, 1) void k3h(const int* __restrict__ qtok,
                                              const int* __restrict__ dtok)
{
    extern __shared__ char smem[];
    const uint32_t sb = smem_u32(smem);
    float* spk = (float*)(smem + K3SPK);
    float* qm  = (float*)(smem + K3QM);
    float* dm  = (float*)(smem + K3DM);

    const int b = blockIdx.x, pair = blockIdx.y;
    const int qi3 = pair / 3, dj3 = pair % 3;
    const int tid = threadIdx.x, lane = tid & 31, wid = tid >> 5;
    const int mi = wid >> 3, wn = wid & 7;

    if (tid < 352) spk[tid] = 0.f;
    if (tid < 32) qm[tid] = (tid < Q_ && qtok[b * Q_ + tid] > 0) ? 1.f : 0.f;
    else if (tid < 288) { int d = tid - 32; dm[d] = (d < D_ && dtok[b * D_ + d] > 0) ? 1.f : 0.f; }

    const __nv_bfloat16* qh = g_qnh + ((size_t)qi3 * QROWS + b * Q_) * C_;
    const __nv_bfloat16* qlp = g_qnl + ((size_t)qi3 * QROWS + b * Q_) * C_;
    const __nv_bfloat16* dh = g_dnh + ((size_t)dj3 * DROWS + b * D_) * C_;
    const __nv_bfloat16* dl = g_dnl + ((size_t)dj3 * DROWS + b * D_) * C_;

    {
        int kc = tid >> 7, row = (tid >> 2) & 31, ch = tid & 3;
        int sz = (row < Q_) ? 16 : 0;
        int srow = (row < Q_) ? row : 0;
        size_t so = (size_t)srow * C_ + kc * 32 + ch * 8;
        uint32_t dst = sb + kc * 2048 + swz(row, ch);
        cpasync16z(dst,          qh  + so, sz);
        cpasync16z(dst + K3Q_LO, qlp + so, sz);
    }

    auto load_d = [&](int kc, int buf) {
#pragma unroll
        for (int j = 0; j < 2; j++) {
            int u = tid + j * 512;
            int row = u >> 2, ch = u & 3;
            int sz = (row < D_) ? 16 : 0;
            int srow = (row < D_) ? row : 0;
            size_t so = (size_t)srow * C_ + kc * 32 + ch * 8;
            uint32_t dst = sb + K3D + buf * 32768 + swz(row, ch);
            cpasync16z(dst,          dh + so, sz);
            cpasync16z(dst + 16384,  dl + so, sz);
        }
        asm volatile("cp.async.commit_group;");
    };

    load_d(0, 0);

    float c[4][4];
#pragma unroll
    for (int i = 0; i < 4; i++)
#pragma unroll
        for (int j = 0; j < 4; j++) c[i][j] = 0.f;

    const int rit = (lane & 7) + ((lane >> 3) & 1) * 8;

    for (int kc = 0; kc < 4; kc++) {
        if (kc < 3) load_d(kc + 1, (kc + 1) & 1);
        if (kc < 3) asm volatile("cp.async.wait_group 1;");
        else        asm volatile("cp.async.wait_group 0;");
        __syncthreads();
        const uint32_t dbB = sb + K3D + (kc & 1) * 32768;
#pragma unroll
        for (int pass = 0; pass < 3; pass++) {
            const uint32_t qB = sb + ((pass == 2) ? K3Q_LO : K3Q_HI) + kc * 2048;
            const uint32_t dB = dbB + ((pass == 1) ? 16384 : 0);
#pragma unroll
            for (int ks = 0; ks < 2; ks++) {
                int kch = ks * 2 + (lane >> 4);
                uint32_t a[4], b0[4], b1[4];
                ldmatrix_x4(a,  qB + swz(mi * 16 + rit, kch));
                ldmatrix_x4(b0, dB + swz(wn * 32 + rit, kch));
                ldmatrix_x4(b1, dB + swz(wn * 32 + 16 + rit, kch));
                mma_bf16(c[0], a, b0[0], b0[2]);
                mma_bf16(c[1], a, b0[1], b0[3]);
                mma_bf16(c[2], a, b1[0], b1[2]);
                mma_bf16(c[3], a, b1[1], b1[3]);
            }
        }
        __syncthreads();
    }

    const float K20 = 28.853901f;       //  20*log2(e)
    const float AW  = -72.134754f;      // -50*log2(e)
    const float A0  = -7.2134754e8f;    // -5e5*log2(e)
    const u64 C4  = dupf(1.8315639e-2f);
    const u64 C8  = dupf(3.3546262e-4f);
    const u64 C12 = dupf(6.1442124e-6f);
    const u64 C16 = dupf(1.1253517e-7f);

#pragma unroll
    for (int s = 0; s < 2; s++) {
        const int row = mi * 16 + (lane >> 2) + s * 8;
        const float qmr = qm[row];
        float pk0 = 0.f;
        u64 pk56 = 0, pk47 = 0, pk38 = 0, pk29 = 0, pk110 = 0;

        float cmv[8], mv[8];
        float maxc = 0.f;
#pragma unroll
        for (int nj = 0; nj < 4; nj++) {
#pragma unroll
            for (int h = 0; h < 2; h++) {
                int idx = nj * 2 + h;
                int col = wn * 32 + nj * 8 + (lane & 3) * 2 + h;
                float m = qmr * dm[col];
                float cm = c[nj][2 * s + h] * m;
                mv[idx] = m; cmv[idx] = cm;
                maxc = fmaxf(maxc, cm);
            }
        }

        // wide kernels: center-out packed chains (3 ex2 per element)
#pragma unroll
        for (int idx = 0; idx < 8; idx++) {
            float m = mv[idx], cm = cmv[idx];
            float arg = cm * K20;
            float t  = ex2f(arg);
            float ti = ex2f(-arg);
            u64 tt = packf(t, ti);
            float dlt = cm - 0.1f;
            float gl = ex2f(dlt * dlt * AW);
            u64 ab = packf(gl, gl * ti);
            u64 m2 = dupf(m);
            ffma2(pk56, m2, ab);
            ab = mul2(ab, tt); ab = mul2(ab, C4);  ffma2(pk47, m2, ab);
            ab = mul2(ab, tt); ab = mul2(ab, C8);  ffma2(pk38, m2, ab);
            ab = mul2(ab, tt); ab = mul2(ab, C12); ffma2(pk29, m2, ab);
            ab = mul2(ab, tt); ab = mul2(ab, C16); ffma2(pk110, m2, ab);
        }

        // exact-match kernel: skipped unless some lane has cm > 0.99
        // (skipped terms are < e^-50 ~ 2e-22; per-kernel sums are clipped at 1e-10
        //  before the log, so the difference is bounded by 4e-20 absolute — harmless)
        if (__any_sync(0xffffffffu, maxc > 0.99f)) {
#pragma unroll
            for (int idx = 0; idx < 8; idx++) {
                float d1 = cmv[idx] - 1.f;
                pk0 = fmaf(mv[idx], ex2f(d1 * d1 * A0), pk0);
            }
        }

#pragma unroll
        for (int o = 1; o <= 2; o <<= 1) {
            pk0  += __shfl_xor_sync(0xffffffffu, pk0, o);
            pk56  = add2(pk56,  __shfl_xor_sync(0xffffffffu, pk56, o));
            pk47  = add2(pk47,  __shfl_xor_sync(0xffffffffu, pk47, o));
            pk38  = add2(pk38,  __shfl_xor_sync(0xffffffffu, pk38, o));
            pk29  = add2(pk29,  __shfl_xor_sync(0xffffffffu, pk29, o));
            pk110 = add2(pk110, __shfl_xor_sync(0xffffffffu, pk110, o));
        }
        if ((lane & 3) == 0) {
            float lo, hi;
            float* rw = spk + row * 11;
            atomicAdd(&rw[0], pk0);
            unpackf(pk56,  lo, hi); atomicAdd(&rw[5], lo); atomicAdd(&rw[6],  hi);
            unpackf(pk47,  lo, hi); atomicAdd(&rw[4], lo); atomicAdd(&rw[7],  hi);
            unpackf(pk38,  lo, hi); atomicAdd(&rw[3], lo); atomicAdd(&rw[8],  hi);
            unpackf(pk29,  lo, hi); atomicAdd(&rw[2], lo); atomicAdd(&rw[9],  hi);
            unpackf(pk110, lo, hi); atomicAdd(&rw[1], lo); atomicAdd(&rw[10], hi);
        }
    }
    __syncthreads();

    if (tid < 11) {
        float f = 0.f;
        for (int q = 0; q < Q_; q++)
            f += logf(fmaxf(spk[q * 11 + tid], 1e-10f)) * 0.01f * qm[q];
        g_feats[(b * 9 + pair) * 11 + tid] = f;
    }
}

// ================= K4: final dense =================
__global__ void k4_out(const float* __restrict__ dw, float* __restrict__ out)
{
    int b = threadIdx.x;
    float f = 0.f;
#pragma unroll
    for (int j = 0; j < 99; j++) f += g_feats[b * 99 + j] * dw[j];
    out[b] = f;
}

// ================= launch =================
extern "C" void kernel_launch(void* const* d_in, const int* in_sizes, int n_in,
                              void* d_out, int out_size)
{
    (void)in_sizes; (void)n_in; (void)out_size;
    const int*   qtok = (const int*)d_in[0];
    const int*   dtok = (const int*)d_in[1];
    const float* emb  = (const float*)d_in[2];
    const float* w1   = (const float*)d_in[3];
    const float* w2   = (const float*)d_in[4];
    const float* w3   = (const float*)d_in[5];
    const float* cb1  = (const float*)d_in[6];
    const float* cb2  = (const float*)d_in[7];
    const float* cb3  = (const float*)d_in[8];
    const float* dw   = (const float*)d_in[9];
    float* out = (float*)d_out;

    cudaFuncSetAttribute(k1h, cudaFuncAttributeMaxDynamicSharedMemorySize, K1_SMEM);
    cudaFuncSetAttribute(k3h, cudaFuncAttributeMaxDynamicSharedMemorySize, K3_SMEM);

    pack_all<<<WBLOCKS + ABLOCKS, 256>>>(w1, w2, w3, emb, qtok, dtok);
    k1h<<<dim3(230, 3), 512, K1_SMEM>>>();
    k2_combine<<<NROWS, 128>>>(cb1, cb2, cb3);
    k3h<<<dim3(128, 9), 512, K3_SMEM>>>(qtok, dtok);
    k4_out<<<1, 128>>>(dw, out);
}

// round 13
// speedup vs baseline: 1.1972x; 1.0601x over previous
#include <cuda_runtime.h>
#include <cuda_bf16.h>
#include <cstdint>

// Problem constants
#define B_    128
#define Q_    30
#define D_    200
#define E_    300
#define C_    128
#define QROWS 3840
#define DROWS 25600
#define NROWS 29440          // 230 * 128
#define NCOLS 768
#define KP    320            // padded K per split-pass

typedef unsigned long long u64;

// ================= f32x2 / misc helpers =================
__device__ __forceinline__ u64 dupf(float x) {
    u64 r; unsigned xi = __float_as_uint(x);
    asm("mov.b64 %0, {%1, %1};" : "=l"(r) : "r"(xi));
    return r;
}
__device__ __forceinline__ u64 packf(float lo, float hi) {
    u64 r; unsigned a = __float_as_uint(lo), b = __float_as_uint(hi);
    asm("mov.b64 %0, {%1, %2};" : "=l"(r) : "r"(a), "r"(b));
    return r;
}
__device__ __forceinline__ void unpackf(u64 v, float& lo, float& hi) {
    unsigned a, b;
    asm("mov.b64 {%0, %1}, %2;" : "=r"(a), "=r"(b) : "l"(v));
    lo = __uint_as_float(a); hi = __uint_as_float(b);
}
__device__ __forceinline__ void ffma2(u64& d, u64 a, u64 b) {
    asm("fma.rn.f32x2 %0, %1, %2, %0;" : "+l"(d) : "l"(a), "l"(b));
}
__device__ __forceinline__ u64 add2(u64 a, u64 b) {
    u64 r; asm("add.rn.f32x2 %0, %1, %2;" : "=l"(r) : "l"(a), "l"(b)); return r;
}
__device__ __forceinline__ u64 mul2(u64 a, u64 b) {
    u64 r; asm("mul.rn.f32x2 %0, %1, %2;" : "=l"(r) : "l"(a), "l"(b)); return r;
}
__device__ __forceinline__ float ex2f(float x) {
    float r; asm("ex2.approx.f32 %0, %1;" : "=f"(r) : "f"(x)); return r;
}
__device__ __forceinline__ void cpasync16(uint32_t sdst, const void* gsrc) {
    asm volatile("cp.async.cg.shared.global [%0], [%1], 16;" :: "r"(sdst), "l"(gsrc));
}
__device__ __forceinline__ void cpasync16z(uint32_t sdst, const void* gsrc, int sz) {
    asm volatile("cp.async.cg.shared.global [%0], [%1], 16, %2;" :: "r"(sdst), "l"(gsrc), "r"(sz));
}
__device__ __forceinline__ uint32_t smem_u32(const void* p) {
    uint32_t a;
    asm("{ .reg .u64 t; cvta.to.shared.u64 t, %1; cvt.u32.u64 %0, t; }" : "=r"(a) : "l"(p));
    return a;
}
__device__ __forceinline__ void ldmatrix_x4(uint32_t* r, uint32_t saddr) {
    asm volatile("ldmatrix.sync.aligned.m8n8.x4.shared.b16 {%0,%1,%2,%3}, [%4];"
                 : "=r"(r[0]), "=r"(r[1]), "=r"(r[2]), "=r"(r[3]) : "r"(saddr));
}
__device__ __forceinline__ void mma_bf16(float* c, const uint32_t* a,
                                         uint32_t b0, uint32_t b1) {
    asm volatile("mma.sync.aligned.m16n8k16.row.col.f32.bf16.bf16.f32 "
                 "{%0,%1,%2,%3}, {%4,%5,%6,%7}, {%8,%9}, {%0,%1,%2,%3};"
                 : "+f"(c[0]), "+f"(c[1]), "+f"(c[2]), "+f"(c[3])
                 : "r"(a[0]), "r"(a[1]), "r"(a[2]), "r"(a[3]), "r"(b0), "r"(b1));
}

// ================= device scratch =================
__device__ __nv_bfloat16 g_Ahi[(size_t)NROWS * KP];
__device__ __nv_bfloat16 g_Alo[(size_t)NROWS * KP];
__device__ __nv_bfloat16 g_Whi[(size_t)NCOLS * KP];
__device__ __nv_bfloat16 g_Wlo[(size_t)NCOLS * KP];
__device__ float g_P[(size_t)NROWS * NCOLS];
__device__ __nv_bfloat16 g_qnh[3 * (size_t)QROWS * C_];
__device__ __nv_bfloat16 g_qnl[3 * (size_t)QROWS * C_];
__device__ __nv_bfloat16 g_dnh[3 * (size_t)DROWS * C_];
__device__ __nv_bfloat16 g_dnl[3 * (size_t)DROWS * C_];
__device__ float g_feats[B_ * 99];

// ================= pack kernel (W + A merged) =================
#define WBLOCKS ((NCOLS * KP + 255) / 256)
#define ABLOCKS ((NROWS * (KP / 4) + 255) / 256)
__global__ void pack_all(const float* __restrict__ w1,
                         const float* __restrict__ w2,
                         const float* __restrict__ w3,
                         const float* __restrict__ emb,
                         const int* __restrict__ qtok,
                         const int* __restrict__ dtok)
{
    if (blockIdx.x < WBLOCKS) {
        int idx = blockIdx.x * 256 + threadIdx.x;
        if (idx >= NCOLS * KP) return;
        int n = idx / KP, k = idx % KP;
        float v = 0.f;
        if (k < E_) {
            if (n < 128)       v = w1[n * E_ + k];
            else if (n < 384) { int u = n - 128; v = w2[(u & 127) * (E_ * 2) + k * 2 + (u >> 7)]; }
            else              { int u = n - 384; v = w3[(u & 127) * (E_ * 3) + k * 3 + (u >> 7)]; }
        }
        __nv_bfloat16 h = __float2bfloat16(v);
        __nv_bfloat16 l = __float2bfloat16(v - __bfloat162float(h));
        g_Whi[idx] = h; g_Wlo[idx] = l;
    } else {
        int idx = (blockIdx.x - WBLOCKS) * 256 + threadIdx.x;
        if (idx >= NROWS * (KP / 4)) return;
        int r = idx / (KP / 4), g = idx % (KP / 4);
        int k = g * 4;
        float4 v = make_float4(0.f, 0.f, 0.f, 0.f);
        if (k < E_) {
            int tok = (r < QROWS) ? qtok[r] : dtok[r - QROWS];
            v = *(const float4*)(emb + (size_t)tok * E_ + k);
        }
        float vv[4] = {v.x, v.y, v.z, v.w};
        u64 hw = 0, lw = 0;
#pragma unroll
        for (int i = 0; i < 4; i++) {
            __nv_bfloat16 h = __float2bfloat16(vv[i]);
            __nv_bfloat16 l = __float2bfloat16(vv[i] - __bfloat162float(h));
            hw |= (u64)(*(unsigned short*)&h) << (16 * i);
            lw |= (u64)(*(unsigned short*)&l) << (16 * i);
        }
        *(u64*)(g_Ahi + (size_t)r * KP + k) = hw;
        *(u64*)(g_Alo + (size_t)r * KP + k) = lw;
    }
}

// ================= K1: HMMA GEMM  P = A' @ W'^T  (bf16 split, K'=960) =================
// CTA tile 128x256, 16 warps (4x4), warp tile 32x64, KC=64, 4-stage cp.async ring.
// Fragment loads software-pipelined: ldmatrix for ks+1 issued before mma of ks.
#define KC        64
#define NCHUNK    15
#define A_BYTES   (128 * 128)      // 128 rows * 128B (64 bf16)
#define B_BYTES   (256 * 128)
#define STAGE_B   (A_BYTES + B_BYTES)
#define K1_SMEM   (4 * STAGE_B)    // 196608

// full SW128 swizzle: 128B rows, 8 x 16B slots, slot ^= (row & 7)
__device__ __forceinline__ uint32_t swz128(int row, int ch) {
    return (uint32_t)(row * 128 + ((ch ^ (row & 7)) << 4));
}
// 64B-row swizzle for k3h tiles
__device__ __forceinline__ uint32_t swz(int row, int ch) {
    return (uint32_t)(row * 64 + ((ch ^ ((row >> 1) & 3)) << 4));
}

__global__ __launch_bounds__(512, 1) void k1h()
{
    extern __shared__ char smem[];
    const uint32_t sb = smem_u32(smem);
    const int tid = threadIdx.x;
    const int lane = tid & 31;
    const int wid = tid >> 5;
    const int warp_m = wid & 3;        // 0..3 (32 rows each)
    const int warp_n = wid >> 2;       // 0..3 (64 cols each)
    const int bm0 = blockIdx.x * 128;
    const int bn0 = blockIdx.y * 256;

    float c[2][8][4];
#pragma unroll
    for (int i = 0; i < 2; i++)
#pragma unroll
        for (int j = 0; j < 8; j++)
#pragma unroll
            for (int k = 0; k < 4; k++) c[i][j][k] = 0.f;

    auto load_stage = [&](int chunk, int st) {
        const int pass = chunk / 5;
        const int kloc = (chunk % 5) * KC;
        const __nv_bfloat16* As = (pass == 2) ? g_Alo : g_Ahi;
        const __nv_bfloat16* Bs = (pass == 1) ? g_Wlo : g_Whi;
        const uint32_t aB = sb + st * STAGE_B;
        const uint32_t bB = aB + A_BYTES;
#pragma unroll
        for (int j = 0; j < 2; j++) {
            int u = tid + j * 512;                 // A: 128 rows x 8 slots = 1024 units
            int row = u >> 3, ch = u & 7;
            cpasync16(aB + swz128(row, ch), As + (size_t)(bm0 + row) * KP + kloc + ch * 8);
        }
#pragma unroll
        for (int j = 0; j < 4; j++) {
            int u = tid + j * 512;                 // B: 256 rows x 8 slots = 2048 units
            int row = u >> 3, ch = u & 7;
            cpasync16(bB + swz128(row, ch), Bs + (size_t)(bn0 + row) * KP + kloc + ch * 8);
        }
        asm volatile("cp.async.commit_group;");
    };

    load_stage(0, 0);
    load_stage(1, 1);

    const int rit = (lane & 7) + ((lane >> 3) & 1) * 8;
    const int kh = lane >> 4;

    for (int cidx = 0; cidx < NCHUNK; cidx++) {
        const int st = cidx & 3;
        if (cidx + 2 < NCHUNK) {
            load_stage(cidx + 2, (cidx + 2) & 3);
            asm volatile("cp.async.wait_group 2;");    // chunk c complete (own copies)
        } else if (cidx + 1 < NCHUNK) {
            asm volatile("cp.async.wait_group 1;");
        } else {
            asm volatile("cp.async.wait_group 0;");
        }
        __syncthreads();                               // cross-thread visibility of chunk c

        const uint32_t aB = sb + st * STAGE_B;
        const uint32_t bB = aB + A_BYTES;

        // double-buffered fragments: load ks+1 before mma(ks)
        uint32_t a[2][2][4], b[2][4][4];
        {
            const int kch = kh;       // ks = 0
#pragma unroll
            for (int mi = 0; mi < 2; mi++)
                ldmatrix_x4(a[0][mi], aB + swz128(warp_m * 32 + mi * 16 + rit, kch));
#pragma unroll
            for (int nj = 0; nj < 4; nj++)
                ldmatrix_x4(b[0][nj], bB + swz128(warp_n * 64 + nj * 16 + rit, kch));
        }
#pragma unroll
        for (int ks = 0; ks < 4; ks++) {
            const int cur = ks & 1, nxt = cur ^ 1;
            if (ks < 3) {
                const int kch = (ks + 1) * 2 + kh;
#pragma unroll
                for (int mi = 0; mi < 2; mi++)
                    ldmatrix_x4(a[nxt][mi], aB + swz128(warp_m * 32 + mi * 16 + rit, kch));
#pragma unroll
                for (int nj = 0; nj < 4; nj++)
                    ldmatrix_x4(b[nxt][nj], bB + swz128(warp_n * 64 + nj * 16 + rit, kch));
            }
#pragma unroll
            for (int mi = 0; mi < 2; mi++)
#pragma unroll
                for (int nj = 0; nj < 4; nj++) {
                    mma_bf16(c[mi][2 * nj],     a[cur][mi], b[cur][nj][0], b[cur][nj][2]);
                    mma_bf16(c[mi][2 * nj + 1], a[cur][mi], b[cur][nj][1], b[cur][nj][3]);
                }
        }
    }

#pragma unroll
    for (int mi = 0; mi < 2; mi++) {
        const int r0 = bm0 + warp_m * 32 + mi * 16 + (lane >> 2);
#pragma unroll
        for (int nj = 0; nj < 4; nj++) {
#pragma unroll
            for (int h = 0; h < 2; h++) {
                const float* cc = c[mi][2 * nj + h];
                const int col = bn0 + warp_n * 64 + nj * 16 + h * 8 + (lane & 3) * 2;
                *(float2*)&g_P[(size_t)r0 * NCOLS + col]       = make_float2(cc[0], cc[1]);
                *(float2*)&g_P[(size_t)(r0 + 8) * NCOLS + col] = make_float2(cc[2], cc[3]);
            }
        }
    }
}

// ================= K2: tap-combine + bias + ReLU + L2-normalize (bf16 split out) =====
__global__ void k2_combine(const float* __restrict__ cb1,
                           const float* __restrict__ cb2,
                           const float* __restrict__ cb3)
{
    const int r = blockIdx.x;
    const int c = threadIdx.x;
    int l, L, rr;
    const bool isq = (r < QROWS);
    if (isq) { rr = r;          l = r % Q_;  L = Q_; }
    else     { rr = r - QROWS;  l = rr % D_; L = D_; }

    const float* Pr = g_P + (size_t)r * NCOLS;
    float v1 = cb1[c] + Pr[c];
    float v2 = cb2[c] + Pr[128 + c];
    float v3 = cb3[c] + Pr[384 + c];
    if (l + 1 < L) { v2 += Pr[NCOLS + 256 + c]; v3 += Pr[NCOLS + 512 + c]; }
    if (l + 2 < L) { v3 += Pr[2 * NCOLS + 640 + c]; }
    v1 = fmaxf(v1, 0.f); v2 = fmaxf(v2, 0.f); v3 = fmaxf(v3, 0.f);

    float s1 = v1 * v1, s2 = v2 * v2, s3 = v3 * v3;
#pragma unroll
    for (int o = 16; o; o >>= 1) {
        s1 += __shfl_xor_sync(0xffffffffu, s1, o);
        s2 += __shfl_xor_sync(0xffffffffu, s2, o);
        s3 += __shfl_xor_sync(0xffffffffu, s3, o);
    }
    __shared__ float sred[3][4];
    const int lane = c & 31, w = c >> 5;
    if (lane == 0) { sred[0][w] = s1; sred[1][w] = s2; sred[2][w] = s3; }
    __syncthreads();
    float ss1 = sred[0][0] + sred[0][1] + sred[0][2] + sred[0][3];
    float ss2 = sred[1][0] + sred[1][1] + sred[1][2] + sred[1][3];
    float ss3 = sred[2][0] + sred[2][1] + sred[2][2] + sred[2][3];
    float n1 = v1 * (1.0f / (sqrtf(ss1) + 1e-13f));
    float n2 = v2 * (1.0f / (sqrtf(ss2) + 1e-13f));
    float n3 = v3 * (1.0f / (sqrtf(ss3) + 1e-13f));

    float nv[3] = {n1, n2, n3};
#pragma unroll
    for (int t = 0; t < 3; t++) {
        __nv_bfloat16 h = __float2bfloat16(nv[t]);
        __nv_bfloat16 lo = __float2bfloat16(nv[t] - __bfloat162float(h));
        if (isq) {
            size_t o = ((size_t)t * QROWS + rr) * C_ + c;
            g_qnh[o] = h; g_qnl[o] = lo;
        } else {
            size_t o = ((size_t)t * DROWS + rr) * C_ + c;
            g_dnh[o] = h; g_dnl[o] = lo;
        }
    }
}

// ================= K3: HMMA cosine GEMM + chain-RBF + log pooling =================
#define K3Q_HI   0
#define K3Q_LO   8192
#define K3D      16384
#define K3SPK    81920
#define K3QM     83328
#define K3DM     83456
#define K3_SMEM  84480

__global__ __launch_bounds__(512, 2) void k3h(const int* __restrict__ qtok,
                                              const int* __restrict__ dtok)
{
    extern __shared__ char smem[];
    const uint32_t sb = smem_u32(smem);
    float* spk = (float*)(smem + K3SPK);
    float* qm  = (float*)(smem + K3QM);
    float* dm  = (float*)(smem + K3DM);

    const int b = blockIdx.x, pair = blockIdx.y;
    const int qi3 = pair / 3, dj3 = pair % 3;
    const int tid = threadIdx.x, lane = tid & 31, wid = tid >> 5;
    const int mi = wid >> 3, wn = wid & 7;

    if (tid < 352) spk[tid] = 0.f;
    if (tid < 32) qm[tid] = (tid < Q_ && qtok[b * Q_ + tid] > 0) ? 1.f : 0.f;
    else if (tid < 288) { int d = tid - 32; dm[d] = (d < D_ && dtok[b * D_ + d] > 0) ? 1.f : 0.f; }

    const __nv_bfloat16* qh = g_qnh + ((size_t)qi3 * QROWS + b * Q_) * C_;
    const __nv_bfloat16* qlp = g_qnl + ((size_t)qi3 * QROWS + b * Q_) * C_;
    const __nv_bfloat16* dh = g_dnh + ((size_t)dj3 * DROWS + b * D_) * C_;
    const __nv_bfloat16* dl = g_dnl + ((size_t)dj3 * DROWS + b * D_) * C_;

    {
        int kc = tid >> 7, row = (tid >> 2) & 31, ch = tid & 3;
        int sz = (row < Q_) ? 16 : 0;
        int srow = (row < Q_) ? row : 0;
        size_t so = (size_t)srow * C_ + kc * 32 + ch * 8;
        uint32_t dst = sb + kc * 2048 + swz(row, ch);
        cpasync16z(dst,          qh  + so, sz);
        cpasync16z(dst + K3Q_LO, qlp + so, sz);
    }

    auto load_d = [&](int kc, int buf) {
#pragma unroll
        for (int j = 0; j < 2; j++) {
            int u = tid + j * 512;
            int row = u >> 2, ch = u & 3;
            int sz = (row < D_) ? 16 : 0;
            int srow = (row < D_) ? row : 0;
            size_t so = (size_t)srow * C_ + kc * 32 + ch * 8;
            uint32_t dst = sb + K3D + buf * 32768 + swz(row, ch);
            cpasync16z(dst,          dh + so, sz);
            cpasync16z(dst + 16384,  dl + so, sz);
        }
        asm volatile("cp.async.commit_group;");
    };

    load_d(0, 0);

    float c[4][4];
#pragma unroll
    for (int i = 0; i < 4; i++)
#pragma unroll
        for (int j = 0; j < 4; j++) c[i][j] = 0.f;

    const int rit = (lane & 7) + ((lane >> 3) & 1) * 8;

    for (int kc = 0; kc < 4; kc++) {
        if (kc < 3) load_d(kc + 1, (kc + 1) & 1);
        if (kc < 3) asm volatile("cp.async.wait_group 1;");
        else        asm volatile("cp.async.wait_group 0;");
        __syncthreads();
        const uint32_t dbB = sb + K3D + (kc & 1) * 32768;
#pragma unroll
        for (int pass = 0; pass < 3; pass++) {
            const uint32_t qB = sb + ((pass == 2) ? K3Q_LO : K3Q_HI) + kc * 2048;
            const uint32_t dB = dbB + ((pass == 1) ? 16384 : 0);
#pragma unroll
            for (int ks = 0; ks < 2; ks++) {
                int kch = ks * 2 + (lane >> 4);
                uint32_t a[4], b0[4], b1[4];
                ldmatrix_x4(a,  qB + swz(mi * 16 + rit, kch));
                ldmatrix_x4(b0, dB + swz(wn * 32 + rit, kch));
                ldmatrix_x4(b1, dB + swz(wn * 32 + 16 + rit, kch));
                mma_bf16(c[0], a, b0[0], b0[2]);
                mma_bf16(c[1], a, b0[1], b0[3]);
                mma_bf16(c[2], a, b1[0], b1[2]);
                mma_bf16(c[3], a, b1[1], b1[3]);
            }
        }
        __syncthreads();
    }

    const float K20 = 28.853901f;       //  20*log2(e)
    const float AW  = -72.134754f;      // -50*log2(e)
    const float A0  = -7.2134754e8f;    // -5e5*log2(e)
    const u64 C4  = dupf(1.8315639e-2f);
    const u64 C8  = dupf(3.3546262e-4f);
    const u64 C12 = dupf(6.1442124e-6f);
    const u64 C16 = dupf(1.1253517e-7f);

#pragma unroll
    for (int s = 0; s < 2; s++) {
        const int row = mi * 16 + (lane >> 2) + s * 8;
        const float qmr = qm[row];
        float pk0 = 0.f;
        u64 pk56 = 0, pk47 = 0, pk38 = 0, pk29 = 0, pk110 = 0;

        float cmv[8], mv[8];
        float maxc = 0.f;
#pragma unroll
        for (int nj = 0; nj < 4; nj++) {
#pragma unroll
            for (int h = 0; h < 2; h++) {
                int idx = nj * 2 + h;
                int col = wn * 32 + nj * 8 + (lane & 3) * 2 + h;
                float m = qmr * dm[col];
                float cm = c[nj][2 * s + h] * m;
                mv[idx] = m; cmv[idx] = cm;
                maxc = fmaxf(maxc, cm);
            }
        }

        // wide kernels: center-out packed chains (3 ex2 per element)
#pragma unroll
        for (int idx = 0; idx < 8; idx++) {
            float m = mv[idx], cm = cmv[idx];
            float arg = cm * K20;
            float t  = ex2f(arg);
            float ti = ex2f(-arg);
            u64 tt = packf(t, ti);
            float dlt = cm - 0.1f;
            float gl = ex2f(dlt * dlt * AW);
            u64 ab = packf(gl, gl * ti);
            u64 m2 = dupf(m);
            ffma2(pk56, m2, ab);
            ab = mul2(ab, tt); ab = mul2(ab, C4);  ffma2(pk47, m2, ab);
            ab = mul2(ab, tt); ab = mul2(ab, C8);  ffma2(pk38, m2, ab);
            ab = mul2(ab, tt); ab = mul2(ab, C12); ffma2(pk29, m2, ab);
            ab = mul2(ab, tt); ab = mul2(ab, C16); ffma2(pk110, m2, ab);
        }

        // exact-match kernel: skipped unless some lane has cm > 0.99
        // (skipped terms are < e^-50 ~ 2e-22; per-kernel sums are clipped at 1e-10
        //  before the log, so the difference is bounded by 4e-20 absolute — harmless)
        if (__any_sync(0xffffffffu, maxc > 0.99f)) {
#pragma unroll
            for (int idx = 0; idx < 8; idx++) {
                float d1 = cmv[idx] - 1.f;
                pk0 = fmaf(mv[idx], ex2f(d1 * d1 * A0), pk0);
            }
        }

#pragma unroll
        for (int o = 1; o <= 2; o <<= 1) {
            pk0  += __shfl_xor_sync(0xffffffffu, pk0, o);
            pk56  = add2(pk56,  __shfl_xor_sync(0xffffffffu, pk56, o));
            pk47  = add2(pk47,  __shfl_xor_sync(0xffffffffu, pk47, o));
            pk38  = add2(pk38,  __shfl_xor_sync(0xffffffffu, pk38, o));
            pk29  = add2(pk29,  __shfl_xor_sync(0xffffffffu, pk29, o));
            pk110 = add2(pk110, __shfl_xor_sync(0xffffffffu, pk110, o));
        }
        if ((lane & 3) == 0) {
            float lo, hi;
            float* rw = spk + row * 11;
            atomicAdd(&rw[0], pk0);
            unpackf(pk56,  lo, hi); atomicAdd(&rw[5], lo); atomicAdd(&rw[6],  hi);
            unpackf(pk47,  lo, hi); atomicAdd(&rw[4], lo); atomicAdd(&rw[7],  hi);
            unpackf(pk38,  lo, hi); atomicAdd(&rw[3], lo); atomicAdd(&rw[8],  hi);
            unpackf(pk29,  lo, hi); atomicAdd(&rw[2], lo); atomicAdd(&rw[9],  hi);
            unpackf(pk110, lo, hi); atomicAdd(&rw[1], lo); atomicAdd(&rw[10], hi);
        }
    }
    __syncthreads();

    if (tid < 11) {
        float f = 0.f;
        for (int q = 0; q < Q_; q++)
            f += logf(fmaxf(spk[q * 11 + tid], 1e-10f)) * 0.01f * qm[q];
        g_feats[(b * 9 + pair) * 11 + tid] = f;
    }
}

// ================= K4: final dense =================
__global__ void k4_out(const float* __restrict__ dw, float* __restrict__ out)
{
    int b = threadIdx.x;
    float f = 0.f;
#pragma unroll
    for (int j = 0; j < 99; j++) f += g_feats[b * 99 + j] * dw[j];
    out[b] = f;
}

// ================= launch =================
extern "C" void kernel_launch(void* const* d_in, const int* in_sizes, int n_in,
                              void* d_out, int out_size)
{
    (void)in_sizes; (void)n_in; (void)out_size;
    const int*   qtok = (const int*)d_in[0];
    const int*   dtok = (const int*)d_in[1];
    const float* emb  = (const float*)d_in[2];
    const float* w1   = (const float*)d_in[3];
    const float* w2   = (const float*)d_in[4];
    const float* w3   = (const float*)d_in[5];
    const float* cb1  = (const float*)d_in[6];
    const float* cb2  = (const float*)d_in[7];
    const float* cb3  = (const float*)d_in[8];
    const float* dw   = (const float*)d_in[9];
    float* out = (float*)d_out;

    cudaFuncSetAttribute(k1h, cudaFuncAttributeMaxDynamicSharedMemorySize, K1_SMEM);
    cudaFuncSetAttribute(k3h, cudaFuncAttributeMaxDynamicSharedMemorySize, K3_SMEM);

    pack_all<<<WBLOCKS + ABLOCKS, 256>>>(w1, w2, w3, emb, qtok, dtok);
    k1h<<<dim3(230, 3), 512, K1_SMEM>>>();
    k2_combine<<<NROWS, 128>>>(cb1, cb2, cb3);
    k3h<<<dim3(128, 9), 512, K3_SMEM>>>(qtok, dtok);
    k4_out<<<1, 128>>>(dw, out);
}

// round 14
// speedup vs baseline: 1.4749x; 1.2319x over previous
#include <cuda_runtime.h>
#include <cuda_bf16.h>
#include <cstdint>

// Problem constants
#define B_    128
#define Q_    30
#define D_    200
#define E_    300
#define C_    128
#define QROWS 3840
#define DROWS 25600
#define NROWS 29440          // 230 * 128
#define NCOLS 768
#define KP    320            // padded K per split-pass

typedef unsigned long long u64;

// ================= f32x2 / misc helpers =================
__device__ __forceinline__ u64 dupf(float x) {
    u64 r; unsigned xi = __float_as_uint(x);
    asm("mov.b64 %0, {%1, %1};" : "=l"(r) : "r"(xi));
    return r;
}
__device__ __forceinline__ u64 packf(float lo, float hi) {
    u64 r; unsigned a = __float_as_uint(lo), b = __float_as_uint(hi);
    asm("mov.b64 %0, {%1, %2};" : "=l"(r) : "r"(a), "r"(b));
    return r;
}
__device__ __forceinline__ void unpackf(u64 v, float& lo, float& hi) {
    unsigned a, b;
    asm("mov.b64 {%0, %1}, %2;" : "=r"(a), "=r"(b) : "l"(v));
    lo = __uint_as_float(a); hi = __uint_as_float(b);
}
__device__ __forceinline__ void ffma2(u64& d, u64 a, u64 b) {
    asm("fma.rn.f32x2 %0, %1, %2, %0;" : "+l"(d) : "l"(a), "l"(b));
}
__device__ __forceinline__ u64 add2(u64 a, u64 b) {
    u64 r; asm("add.rn.f32x2 %0, %1, %2;" : "=l"(r) : "l"(a), "l"(b)); return r;
}
__device__ __forceinline__ u64 mul2(u64 a, u64 b) {
    u64 r; asm("mul.rn.f32x2 %0, %1, %2;" : "=l"(r) : "l"(a), "l"(b)); return r;
}
__device__ __forceinline__ float ex2f(float x) {
    float r; asm("ex2.approx.f32 %0, %1;" : "=f"(r) : "f"(x)); return r;
}
__device__ __forceinline__ void cpasync16(uint32_t sdst, const void* gsrc) {
    asm volatile("cp.async.cg.shared.global [%0], [%1], 16;" :: "r"(sdst), "l"(gsrc));
}
__device__ __forceinline__ void cpasync16z(uint32_t sdst, const void* gsrc, int sz) {
    asm volatile("cp.async.cg.shared.global [%0], [%1], 16, %2;" :: "r"(sdst), "l"(gsrc), "r"(sz));
}
__device__ __forceinline__ uint32_t smem_u32(const void* p) {
    uint32_t a;
    asm("{ .reg .u64 t; cvta.to.shared.u64 t, %1; cvt.u32.u64 %0, t; }" : "=r"(a) : "l"(p));
    return a;
}
__device__ __forceinline__ void ldmatrix_x4(uint32_t* r, uint32_t saddr) {
    asm volatile("ldmatrix.sync.aligned.m8n8.x4.shared.b16 {%0,%1,%2,%3}, [%4];"
                 : "=r"(r[0]), "=r"(r[1]), "=r"(r[2]), "=r"(r[3]) : "r"(saddr));
}
__device__ __forceinline__ void mma_bf16(float* c, const uint32_t* a,
                                         uint32_t b0, uint32_t b1) {
    asm volatile("mma.sync.aligned.m16n8k16.row.col.f32.bf16.bf16.f32 "
                 "{%0,%1,%2,%3}, {%4,%5,%6,%7}, {%8,%9}, {%0,%1,%2,%3};"
                 : "+f"(c[0]), "+f"(c[1]), "+f"(c[2]), "+f"(c[3])
                 : "r"(a[0]), "r"(a[1]), "r"(a[2]), "r"(a[3]), "r"(b0), "r"(b1));
}

// ================= device scratch =================
__device__ __nv_bfloat16 g_Ahi[(size_t)NROWS * KP];
__device__ __nv_bfloat16 g_Whi[(size_t)NCOLS * KP];
__device__ __nv_bfloat16 g_Wlo[(size_t)NCOLS * KP];
__device__ __nv_bfloat16 g_P[(size_t)NROWS * NCOLS];     // bf16 conv partials
__device__ __nv_bfloat16 g_qnh[3 * (size_t)QROWS * C_];
__device__ __nv_bfloat16 g_qnl[3 * (size_t)QROWS * C_];
__device__ __nv_bfloat16 g_dnh[3 * (size_t)DROWS * C_];
__device__ __nv_bfloat16 g_dnl[3 * (size_t)DROWS * C_];
__device__ float g_feats[B_ * 99];

// ================= pack kernel (W + A merged) =================
#define WBLOCKS ((NCOLS * KP + 255) / 256)
#define ABLOCKS ((NROWS * (KP / 4) + 255) / 256)
__global__ void pack_all(const float* __restrict__ w1,
                         const float* __restrict__ w2,
                         const float* __restrict__ w3,
                         const float* __restrict__ emb,
                         const int* __restrict__ qtok,
                         const int* __restrict__ dtok)
{
    if (blockIdx.x < WBLOCKS) {
        int idx = blockIdx.x * 256 + threadIdx.x;
        if (idx >= NCOLS * KP) return;
        int n = idx / KP, k = idx % KP;
        float v = 0.f;
        if (k < E_) {
            if (n < 128)       v = w1[n * E_ + k];
            else if (n < 384) { int u = n - 128; v = w2[(u & 127) * (E_ * 2) + k * 2 + (u >> 7)]; }
            else              { int u = n - 384; v = w3[(u & 127) * (E_ * 3) + k * 3 + (u >> 7)]; }
        }
        __nv_bfloat16 h = __float2bfloat16(v);
        __nv_bfloat16 l = __float2bfloat16(v - __bfloat162float(h));
        g_Whi[idx] = h; g_Wlo[idx] = l;
    } else {
        int idx = (blockIdx.x - WBLOCKS) * 256 + threadIdx.x;
        if (idx >= NROWS * (KP / 4)) return;
        int r = idx / (KP / 4), g = idx % (KP / 4);
        int k = g * 4;
        float4 v = make_float4(0.f, 0.f, 0.f, 0.f);
        if (k < E_) {
            int tok = (r < QROWS) ? qtok[r] : dtok[r - QROWS];
            v = *(const float4*)(emb + (size_t)tok * E_ + k);
        }
        float vv[4] = {v.x, v.y, v.z, v.w};
        u64 hw = 0;
#pragma unroll
        for (int i = 0; i < 4; i++) {
            __nv_bfloat16 h = __float2bfloat16(vv[i]);
            hw |= (u64)(*(unsigned short*)&h) << (16 * i);
        }
        *(u64*)(g_Ahi + (size_t)r * KP + k) = hw;
    }
}

// ================= K1: HMMA GEMM  P = A_hi @ (W_hi + W_lo)^T  (2 passes, K'=640) =====
// CTA tile 128x256, 16 warps (4x4), warp tile 32x64, KC=64, 4-stage cp.async ring.
#define KC        64
#define NCHUNK    10
#define A_BYTES   (128 * 128)      // 128 rows * 128B (64 bf16)
#define B_BYTES   (256 * 128)
#define STAGE_B   (A_BYTES + B_BYTES)
#define K1_SMEM   (4 * STAGE_B)    // 196608

// full SW128 swizzle: 128B rows, 8 x 16B slots, slot ^= (row & 7)
__device__ __forceinline__ uint32_t swz128(int row, int ch) {
    return (uint32_t)(row * 128 + ((ch ^ (row & 7)) << 4));
}
// 64B-row swizzle for k3h tiles
__device__ __forceinline__ uint32_t swz(int row, int ch) {
    return (uint32_t)(row * 64 + ((ch ^ ((row >> 1) & 3)) << 4));
}

__global__ __launch_bounds__(512, 1) void k1h()
{
    extern __shared__ char smem[];
    const uint32_t sb = smem_u32(smem);
    const int tid = threadIdx.x;
    const int lane = tid & 31;
    const int wid = tid >> 5;
    const int warp_m = wid & 3;        // 0..3 (32 rows each)
    const int warp_n = wid >> 2;       // 0..3 (64 cols each)
    const int bm0 = blockIdx.x * 128;
    const int bn0 = blockIdx.y * 256;

    float c[2][8][4];
#pragma unroll
    for (int i = 0; i < 2; i++)
#pragma unroll
        for (int j = 0; j < 8; j++)
#pragma unroll
            for (int k = 0; k < 4; k++) c[i][j][k] = 0.f;

    auto load_stage = [&](int chunk, int st) {
        const int pass = chunk / 5;
        const int kloc = (chunk % 5) * KC;
        const __nv_bfloat16* Bs = (pass == 1) ? g_Wlo : g_Whi;
        const uint32_t aB = sb + st * STAGE_B;
        const uint32_t bB = aB + A_BYTES;
#pragma unroll
        for (int j = 0; j < 2; j++) {
            int u = tid + j * 512;                 // A: 128 rows x 8 slots = 1024 units
            int row = u >> 3, ch = u & 7;
            cpasync16(aB + swz128(row, ch), g_Ahi + (size_t)(bm0 + row) * KP + kloc + ch * 8);
        }
#pragma unroll
        for (int j = 0; j < 4; j++) {
            int u = tid + j * 512;                 // B: 256 rows x 8 slots = 2048 units
            int row = u >> 3, ch = u & 7;
            cpasync16(bB + swz128(row, ch), Bs + (size_t)(bn0 + row) * KP + kloc + ch * 8);
        }
        asm volatile("cp.async.commit_group;");
    };

    load_stage(0, 0);
    load_stage(1, 1);

    const int rit = (lane & 7) + ((lane >> 3) & 1) * 8;
    const int kh = lane >> 4;

    for (int cidx = 0; cidx < NCHUNK; cidx++) {
        const int st = cidx & 3;
        if (cidx + 2 < NCHUNK) {
            load_stage(cidx + 2, (cidx + 2) & 3);
            asm volatile("cp.async.wait_group 2;");    // chunk c complete (own copies)
        } else if (cidx + 1 < NCHUNK) {
            asm volatile("cp.async.wait_group 1;");
        } else {
            asm volatile("cp.async.wait_group 0;");
        }
        __syncthreads();                               // cross-thread visibility of chunk c

        const uint32_t aB = sb + st * STAGE_B;
        const uint32_t bB = aB + A_BYTES;

        uint32_t a[2][2][4], b[2][4][4];
        {
            const int kch = kh;       // ks = 0
#pragma unroll
            for (int mi = 0; mi < 2; mi++)
                ldmatrix_x4(a[0][mi], aB + swz128(warp_m * 32 + mi * 16 + rit, kch));
#pragma unroll
            for (int nj = 0; nj < 4; nj++)
                ldmatrix_x4(b[0][nj], bB + swz128(warp_n * 64 + nj * 16 + rit, kch));
        }
#pragma unroll
        for (int ks = 0; ks < 4; ks++) {
            const int cur = ks & 1, nxt = cur ^ 1;
            if (ks < 3) {
                const int kch = (ks + 1) * 2 + kh;
#pragma unroll
                for (int mi = 0; mi < 2; mi++)
                    ldmatrix_x4(a[nxt][mi], aB + swz128(warp_m * 32 + mi * 16 + rit, kch));
#pragma unroll
                for (int nj = 0; nj < 4; nj++)
                    ldmatrix_x4(b[nxt][nj], bB + swz128(warp_n * 64 + nj * 16 + rit, kch));
            }
#pragma unroll
            for (int mi = 0; mi < 2; mi++)
#pragma unroll
                for (int nj = 0; nj < 4; nj++) {
                    mma_bf16(c[mi][2 * nj],     a[cur][mi], b[cur][nj][0], b[cur][nj][2]);
                    mma_bf16(c[mi][2 * nj + 1], a[cur][mi], b[cur][nj][1], b[cur][nj][3]);
                }
        }
    }

    // epilogue: convert fp32 acc -> bf16 pairs, store 4B per (row, col-pair)
#pragma unroll
    for (int mi = 0; mi < 2; mi++) {
        const int r0 = bm0 + warp_m * 32 + mi * 16 + (lane >> 2);
#pragma unroll
        for (int nj = 0; nj < 4; nj++) {
#pragma unroll
            for (int h = 0; h < 2; h++) {
                const float* cc = c[mi][2 * nj + h];
                const int col = bn0 + warp_n * 64 + nj * 16 + h * 8 + (lane & 3) * 2;
                __nv_bfloat162 p0 = __float22bfloat162_rn(make_float2(cc[0], cc[1]));
                __nv_bfloat162 p1 = __float22bfloat162_rn(make_float2(cc[2], cc[3]));
                *(__nv_bfloat162*)&g_P[(size_t)r0 * NCOLS + col]       = p0;
                *(__nv_bfloat162*)&g_P[(size_t)(r0 + 8) * NCOLS + col] = p1;
            }
        }
    }
}

// ================= K2: tap-combine + bias + ReLU + L2-normalize (bf16 in/out) =====
__global__ void k2_combine(const float* __restrict__ cb1,
                           const float* __restrict__ cb2,
                           const float* __restrict__ cb3)
{
    const int r = blockIdx.x;
    const int c = threadIdx.x;
    int l, L, rr;
    const bool isq = (r < QROWS);
    if (isq) { rr = r;          l = r % Q_;  L = Q_; }
    else     { rr = r - QROWS;  l = rr % D_; L = D_; }

    const __nv_bfloat16* Pr = g_P + (size_t)r * NCOLS;
    float v1 = cb1[c] + __bfloat162float(Pr[c]);
    float v2 = cb2[c] + __bfloat162float(Pr[128 + c]);
    float v3 = cb3[c] + __bfloat162float(Pr[384 + c]);
    if (l + 1 < L) {
        v2 += __bfloat162float(Pr[NCOLS + 256 + c]);
        v3 += __bfloat162float(Pr[NCOLS + 512 + c]);
    }
    if (l + 2 < L) v3 += __bfloat162float(Pr[2 * NCOLS + 640 + c]);
    v1 = fmaxf(v1, 0.f); v2 = fmaxf(v2, 0.f); v3 = fmaxf(v3, 0.f);

    float s1 = v1 * v1, s2 = v2 * v2, s3 = v3 * v3;
#pragma unroll
    for (int o = 16; o; o >>= 1) {
        s1 += __shfl_xor_sync(0xffffffffu, s1, o);
        s2 += __shfl_xor_sync(0xffffffffu, s2, o);
        s3 += __shfl_xor_sync(0xffffffffu, s3, o);
    }
    __shared__ float sred[3][4];
    const int lane = c & 31, w = c >> 5;
    if (lane == 0) { sred[0][w] = s1; sred[1][w] = s2; sred[2][w] = s3; }
    __syncthreads();
    float ss1 = sred[0][0] + sred[0][1] + sred[0][2] + sred[0][3];
    float ss2 = sred[1][0] + sred[1][1] + sred[1][2] + sred[1][3];
    float ss3 = sred[2][0] + sred[2][1] + sred[2][2] + sred[2][3];
    float n1 = v1 * (1.0f / (sqrtf(ss1) + 1e-13f));
    float n2 = v2 * (1.0f / (sqrtf(ss2) + 1e-13f));
    float n3 = v3 * (1.0f / (sqrtf(ss3) + 1e-13f));

    float nv[3] = {n1, n2, n3};
#pragma unroll
    for (int t = 0; t < 3; t++) {
        __nv_bfloat16 h = __float2bfloat16(nv[t]);
        __nv_bfloat16 lo = __float2bfloat16(nv[t] - __bfloat162float(h));
        if (isq) {
            size_t o = ((size_t)t * QROWS + rr) * C_ + c;
            g_qnh[o] = h; g_qnl[o] = lo;
        } else {
            size_t o = ((size_t)t * DROWS + rr) * C_ + c;
            g_dnh[o] = h; g_dnl[o] = lo;
        }
    }
}

// ================= K3: HMMA cosine GEMM + chain-RBF + log pooling =================
#define K3Q_HI   0
#define K3Q_LO   8192
#define K3D      16384
#define K3SPK    81920
#define K3QM     83328
#define K3DM     83456
#define K3_SMEM  84480

__global__ __launch_bounds__(512, 2) void k3h(const int* __restrict__ qtok,
                                              const int* __restrict__ dtok)
{
    extern __shared__ char smem[];
    const uint32_t sb = smem_u32(smem);
    float* spk = (float*)(smem + K3SPK);
    float* qm  = (float*)(smem + K3QM);
    float* dm  = (float*)(smem + K3DM);

    const int b = blockIdx.x, pair = blockIdx.y;
    const int qi3 = pair / 3, dj3 = pair % 3;
    const int tid = threadIdx.x, lane = tid & 31, wid = tid >> 5;
    const int mi = wid >> 3, wn = wid & 7;

    if (tid < 352) spk[tid] = 0.f;
    if (tid < 32) qm[tid] = (tid < Q_ && qtok[b * Q_ + tid] > 0) ? 1.f : 0.f;
    else if (tid < 288) { int d = tid - 32; dm[d] = (d < D_ && dtok[b * D_ + d] > 0) ? 1.f : 0.f; }

    const __nv_bfloat16* qh = g_qnh + ((size_t)qi3 * QROWS + b * Q_) * C_;
    const __nv_bfloat16* qlp = g_qnl + ((size_t)qi3 * QROWS + b * Q_) * C_;
    const __nv_bfloat16* dh = g_dnh + ((size_t)dj3 * DROWS + b * D_) * C_;
    const __nv_bfloat16* dl = g_dnl + ((size_t)dj3 * DROWS + b * D_) * C_;

    {
        int kc = tid >> 7, row = (tid >> 2) & 31, ch = tid & 3;
        int sz = (row < Q_) ? 16 : 0;
        int srow = (row < Q_) ? row : 0;
        size_t so = (size_t)srow * C_ + kc * 32 + ch * 8;
        uint32_t dst = sb + kc * 2048 + swz(row, ch);
        cpasync16z(dst,          qh  + so, sz);
        cpasync16z(dst + K3Q_LO, qlp + so, sz);
    }

    auto load_d = [&](int kc, int buf) {
#pragma unroll
        for (int j = 0; j < 2; j++) {
            int u = tid + j * 512;
            int row = u >> 2, ch = u & 3;
            int sz = (row < D_) ? 16 : 0;
            int srow = (row < D_) ? row : 0;
            size_t so = (size_t)srow * C_ + kc * 32 + ch * 8;
            uint32_t dst = sb + K3D + buf * 32768 + swz(row, ch);
            cpasync16z(dst,          dh + so, sz);
            cpasync16z(dst + 16384,  dl + so, sz);
        }
        asm volatile("cp.async.commit_group;");
    };

    load_d(0, 0);

    float c[4][4];
#pragma unroll
    for (int i = 0; i < 4; i++)
#pragma unroll
        for (int j = 0; j < 4; j++) c[i][j] = 0.f;

    const int rit = (lane & 7) + ((lane >> 3) & 1) * 8;

    for (int kc = 0; kc < 4; kc++) {
        if (kc < 3) load_d(kc + 1, (kc + 1) & 1);
        if (kc < 3) asm volatile("cp.async.wait_group 1;");
        else        asm volatile("cp.async.wait_group 0;");
        __syncthreads();
        const uint32_t dbB = sb + K3D + (kc & 1) * 32768;
#pragma unroll
        for (int pass = 0; pass < 3; pass++) {
            const uint32_t qB = sb + ((pass == 2) ? K3Q_LO : K3Q_HI) + kc * 2048;
            const uint32_t dB = dbB + ((pass == 1) ? 16384 : 0);
#pragma unroll
            for (int ks = 0; ks < 2; ks++) {
                int kch = ks * 2 + (lane >> 4);
                uint32_t a[4], b0[4], b1[4];
                ldmatrix_x4(a,  qB + swz(mi * 16 + rit, kch));
                ldmatrix_x4(b0, dB + swz(wn * 32 + rit, kch));
                ldmatrix_x4(b1, dB + swz(wn * 32 + 16 + rit, kch));
                mma_bf16(c[0], a, b0[0], b0[2]);
                mma_bf16(c[1], a, b0[1], b0[3]);
                mma_bf16(c[2], a, b1[0], b1[2]);
                mma_bf16(c[3], a, b1[1], b1[3]);
            }
        }
        __syncthreads();
    }

    const float K20 = 28.853901f;       //  20*log2(e)
    const float AW  = -72.134754f;      // -50*log2(e)
    const float A0  = -7.2134754e8f;    // -5e5*log2(e)
    const u64 C4  = dupf(1.8315639e-2f);
    const u64 C8  = dupf(3.3546262e-4f);
    const u64 C12 = dupf(6.1442124e-6f);
    const u64 C16 = dupf(1.1253517e-7f);

#pragma unroll
    for (int s = 0; s < 2; s++) {
        const int row = mi * 16 + (lane >> 2) + s * 8;
        const float qmr = qm[row];
        float pk0 = 0.f;
        u64 pk56 = 0, pk47 = 0, pk38 = 0, pk29 = 0, pk110 = 0;

        float cmv[8], mv[8];
        float maxc = 0.f;
#pragma unroll
        for (int nj = 0; nj < 4; nj++) {
#pragma unroll
            for (int h = 0; h < 2; h++) {
                int idx = nj * 2 + h;
                int col = wn * 32 + nj * 8 + (lane & 3) * 2 + h;
                float m = qmr * dm[col];
                float cm = c[nj][2 * s + h] * m;
                mv[idx] = m; cmv[idx] = cm;
                maxc = fmaxf(maxc, cm);
            }
        }

        // wide kernels: center-out packed chains (3 ex2 per element)
#pragma unroll
        for (int idx = 0; idx < 8; idx++) {
            float m = mv[idx], cm = cmv[idx];
            float arg = cm * K20;
            float t  = ex2f(arg);
            float ti = ex2f(-arg);
            u64 tt = packf(t, ti);
            float dlt = cm - 0.1f;
            float gl = ex2f(dlt * dlt * AW);
            u64 ab = packf(gl, gl * ti);
            u64 m2 = dupf(m);
            ffma2(pk56, m2, ab);
            ab = mul2(ab, tt); ab = mul2(ab, C4);  ffma2(pk47, m2, ab);
            ab = mul2(ab, tt); ab = mul2(ab, C8);  ffma2(pk38, m2, ab);
            ab = mul2(ab, tt); ab = mul2(ab, C12); ffma2(pk29, m2, ab);
            ab = mul2(ab, tt); ab = mul2(ab, C16); ffma2(pk110, m2, ab);
        }

        // exact-match kernel: skipped unless some lane has cm > 0.99
        if (__any_sync(0xffffffffu, maxc > 0.99f)) {
#pragma unroll
            for (int idx = 0; idx < 8; idx++) {
                float d1 = cmv[idx] - 1.f;
                pk0 = fmaf(mv[idx], ex2f(d1 * d1 * A0), pk0);
            }
        }

#pragma unroll
        for (int o = 1; o <= 2; o <<= 1) {
            pk0  += __shfl_xor_sync(0xffffffffu, pk0, o);
            pk56  = add2(pk56,  __shfl_xor_sync(0xffffffffu, pk56, o));
            pk47  = add2(pk47,  __shfl_xor_sync(0xffffffffu, pk47, o));
            pk38  = add2(pk38,  __shfl_xor_sync(0xffffffffu, pk38, o));
            pk29  = add2(pk29,  __shfl_xor_sync(0xffffffffu, pk29, o));
            pk110 = add2(pk110, __shfl_xor_sync(0xffffffffu, pk110, o));
        }
        if ((lane & 3) == 0) {
            float lo, hi;
            float* rw = spk + row * 11;
            atomicAdd(&rw[0], pk0);
            unpackf(pk56,  lo, hi); atomicAdd(&rw[5], lo); atomicAdd(&rw[6],  hi);
            unpackf(pk47,  lo, hi); atomicAdd(&rw[4], lo); atomicAdd(&rw[7],  hi);
            unpackf(pk38,  lo, hi); atomicAdd(&rw[3], lo); atomicAdd(&rw[8],  hi);
            unpackf(pk29,  lo, hi); atomicAdd(&rw[2], lo); atomicAdd(&rw[9],  hi);
            unpackf(pk110, lo, hi); atomicAdd(&rw[1], lo); atomicAdd(&rw[10], hi);
        }
    }
    __syncthreads();

    if (tid < 11) {
        float f = 0.f;
        for (int q = 0; q < Q_; q++)
            f += logf(fmaxf(spk[q * 11 + tid], 1e-10f)) * 0.01f * qm[q];
        g_feats[(b * 9 + pair) * 11 + tid] = f;
    }
}

// ================= K4: final dense =================
__global__ void k4_out(const float* __restrict__ dw, float* __restrict__ out)
{
    int b = threadIdx.x;
    float f = 0.f;
#pragma unroll
    for (int j = 0; j < 99; j++) f += g_feats[b * 99 + j] * dw[j];
    out[b] = f;
}

// ================= launch =================
extern "C" void kernel_launch(void* const* d_in, const int* in_sizes, int n_in,
                              void* d_out, int out_size)
{
    (void)in_sizes; (void)n_in; (void)out_size;
    const int*   qtok = (const int*)d_in[0];
    const int*   dtok = (const int*)d_in[1];
    const float* emb  = (const float*)d_in[2];
    const float* w1   = (const float*)d_in[3];
    const float* w2   = (const float*)d_in[4];
    const float* w3   = (const float*)d_in[5];
    const float* cb1  = (const float*)d_in[6];
    const float* cb2  = (const float*)d_in[7];
    const float* cb3  = (const float*)d_in[8];
    const float* dw   = (const float*)d_in[9];
    float* out = (float*)d_out;

    cudaFuncSetAttribute(k1h, cudaFuncAttributeMaxDynamicSharedMemorySize, K1_SMEM);
    cudaFuncSetAttribute(k3h, cudaFuncAttributeMaxDynamicSharedMemorySize, K3_SMEM);

    pack_all<<<WBLOCKS + ABLOCKS, 256>>>(w1, w2, w3, emb, qtok, dtok);
    k1h<<<dim3(230, 3), 512, K1_SMEM>>>();
    k2_combine<<<NROWS, 128>>>(cb1, cb2, cb3);
    k3h<<<dim3(128, 9), 512, K3_SMEM>>>(qtok, dtok);
    k4_out<<<1, 128>>>(dw, out);
}

// round 15
// speedup vs baseline: 1.8754x; 1.2715x over previous
#include <cuda_runtime.h>
#include <cuda_bf16.h>
#include <cstdint>

// Problem constants
#define B_    128
#define Q_    30
#define D_    200
#define E_    300
#define C_    128
#define QROWS 3840
#define DROWS 25600
#define NROWS 29440          // 230 * 128
#define NCOLS 768
#define KP    320            // padded K

typedef unsigned long long u64;

// ================= f32x2 / misc helpers =================
__device__ __forceinline__ u64 dupf(float x) {
    u64 r; unsigned xi = __float_as_uint(x);
    asm("mov.b64 %0, {%1, %1};" : "=l"(r) : "r"(xi));
    return r;
}
__device__ __forceinline__ u64 packf(float lo, float hi) {
    u64 r; unsigned a = __float_as_uint(lo), b = __float_as_uint(hi);
    asm("mov.b64 %0, {%1, %2};" : "=l"(r) : "r"(a), "r"(b));
    return r;
}
__device__ __forceinline__ void unpackf(u64 v, float& lo, float& hi) {
    unsigned a, b;
    asm("mov.b64 {%0, %1}, %2;" : "=r"(a), "=r"(b) : "l"(v));
    lo = __uint_as_float(a); hi = __uint_as_float(b);
}
__device__ __forceinline__ void ffma2(u64& d, u64 a, u64 b) {
    asm("fma.rn.f32x2 %0, %1, %2, %0;" : "+l"(d) : "l"(a), "l"(b));
}
__device__ __forceinline__ u64 add2(u64 a, u64 b) {
    u64 r; asm("add.rn.f32x2 %0, %1, %2;" : "=l"(r) : "l"(a), "l"(b)); return r;
}
__device__ __forceinline__ u64 mul2(u64 a, u64 b) {
    u64 r; asm("mul.rn.f32x2 %0, %1, %2;" : "=l"(r) : "l"(a), "l"(b)); return r;
}
__device__ __forceinline__ float ex2f(float x) {
    float r; asm("ex2.approx.f32 %0, %1;" : "=f"(r) : "f"(x)); return r;
}
__device__ __forceinline__ void cpasync16(uint32_t sdst, const void* gsrc) {
    asm volatile("cp.async.cg.shared.global [%0], [%1], 16;" :: "r"(sdst), "l"(gsrc));
}
__device__ __forceinline__ void cpasync16z(uint32_t sdst, const void* gsrc, int sz) {
    asm volatile("cp.async.cg.shared.global [%0], [%1], 16, %2;" :: "r"(sdst), "l"(gsrc), "r"(sz));
}
__device__ __forceinline__ uint32_t smem_u32(const void* p) {
    uint32_t a;
    asm("{ .reg .u64 t; cvta.to.shared.u64 t, %1; cvt.u32.u64 %0, t; }" : "=r"(a) : "l"(p));
    return a;
}
__device__ __forceinline__ void ldmatrix_x4(uint32_t* r, uint32_t saddr) {
    asm volatile("ldmatrix.sync.aligned.m8n8.x4.shared.b16 {%0,%1,%2,%3}, [%4];"
                 : "=r"(r[0]), "=r"(r[1]), "=r"(r[2]), "=r"(r[3]) : "r"(saddr));
}
__device__ __forceinline__ void mma_bf16(float* c, const uint32_t* a,
                                         uint32_t b0, uint32_t b1) {
    asm volatile("mma.sync.aligned.m16n8k16.row.col.f32.bf16.bf16.f32 "
                 "{%0,%1,%2,%3}, {%4,%5,%6,%7}, {%8,%9}, {%0,%1,%2,%3};"
                 : "+f"(c[0]), "+f"(c[1]), "+f"(c[2]), "+f"(c[3])
                 : "r"(a[0]), "r"(a[1]), "r"(a[2]), "r"(a[3]), "r"(b0), "r"(b1));
}

// ================= device scratch =================
__device__ __nv_bfloat16 g_Ahi[(size_t)NROWS * KP];
__device__ __nv_bfloat16 g_Whi[(size_t)NCOLS * KP];
__device__ __nv_bfloat16 g_P[(size_t)NROWS * NCOLS];     // bf16 conv partials
__device__ __nv_bfloat16 g_qnh[3 * (size_t)QROWS * C_];
__device__ __nv_bfloat16 g_qnl[3 * (size_t)QROWS * C_];
__device__ __nv_bfloat16 g_dnh[3 * (size_t)DROWS * C_];
__device__ __nv_bfloat16 g_dnl[3 * (size_t)DROWS * C_];
__device__ float g_feats[B_ * 99];

// ================= pack kernel (W + A merged) =================
#define WBLOCKS ((NCOLS * KP + 255) / 256)
#define ABLOCKS ((NROWS * (KP / 4) + 255) / 256)
__global__ void pack_all(const float* __restrict__ w1,
                         const float* __restrict__ w2,
                         const float* __restrict__ w3,
                         const float* __restrict__ emb,
                         const int* __restrict__ qtok,
                         const int* __restrict__ dtok)
{
    if (blockIdx.x < WBLOCKS) {
        int idx = blockIdx.x * 256 + threadIdx.x;
        if (idx >= NCOLS * KP) return;
        int n = idx / KP, k = idx % KP;
        float v = 0.f;
        if (k < E_) {
            if (n < 128)       v = w1[n * E_ + k];
            else if (n < 384) { int u = n - 128; v = w2[(u & 127) * (E_ * 2) + k * 2 + (u >> 7)]; }
            else              { int u = n - 384; v = w3[(u & 127) * (E_ * 3) + k * 3 + (u >> 7)]; }
        }
        g_Whi[idx] = __float2bfloat16(v);
    } else {
        int idx = (blockIdx.x - WBLOCKS) * 256 + threadIdx.x;
        if (idx >= NROWS * (KP / 4)) return;
        int r = idx / (KP / 4), g = idx % (KP / 4);
        int k = g * 4;
        float4 v = make_float4(0.f, 0.f, 0.f, 0.f);
        if (k < E_) {
            int tok = (r < QROWS) ? qtok[r] : dtok[r - QROWS];
            v = *(const float4*)(emb + (size_t)tok * E_ + k);
        }
        float vv[4] = {v.x, v.y, v.z, v.w};
        u64 hw = 0;
#pragma unroll
        for (int i = 0; i < 4; i++) {
            __nv_bfloat16 h = __float2bfloat16(vv[i]);
            hw |= (u64)(*(unsigned short*)&h) << (16 * i);
        }
        *(u64*)(g_Ahi + (size_t)r * KP + k) = hw;
    }
}

// ================= K1: HMMA GEMM  P = A_hi @ W_hi^T  (single pass, K=320) =====
// CTA tile 128x256, 16 warps (4x4), warp tile 32x64, KC=64, 4-stage cp.async ring.
#define KC        64
#define NCHUNK    5
#define A_BYTES   (128 * 128)      // 128 rows * 128B (64 bf16)
#define B_BYTES   (256 * 128)
#define STAGE_B   (A_BYTES + B_BYTES)
#define K1_SMEM   (4 * STAGE_B)    // 196608

// full SW128 swizzle: 128B rows, 8 x 16B slots, slot ^= (row & 7)
__device__ __forceinline__ uint32_t swz128(int row, int ch) {
    return (uint32_t)(row * 128 + ((ch ^ (row & 7)) << 4));
}
// 64B-row swizzle for k3h tiles
__device__ __forceinline__ uint32_t swz(int row, int ch) {
    return (uint32_t)(row * 64 + ((ch ^ ((row >> 1) & 3)) << 4));
}

__global__ __launch_bounds__(512, 1) void k1h()
{
    extern __shared__ char smem[];
    const uint32_t sb = smem_u32(smem);
    const int tid = threadIdx.x;
    const int lane = tid & 31;
    const int wid = tid >> 5;
    const int warp_m = wid & 3;        // 0..3 (32 rows each)
    const int warp_n = wid >> 2;       // 0..3 (64 cols each)
    const int bm0 = blockIdx.x * 128;
    const int bn0 = blockIdx.y * 256;

    float c[2][8][4];
#pragma unroll
    for (int i = 0; i < 2; i++)
#pragma unroll
        for (int j = 0; j < 8; j++)
#pragma unroll
            for (int k = 0; k < 4; k++) c[i][j][k] = 0.f;

    auto load_stage = [&](int chunk, int st) {
        const int kloc = chunk * KC;
        const uint32_t aB = sb + st * STAGE_B;
        const uint32_t bB = aB + A_BYTES;
#pragma unroll
        for (int j = 0; j < 2; j++) {
            int u = tid + j * 512;                 // A: 128 rows x 8 slots = 1024 units
            int row = u >> 3, ch = u & 7;
            cpasync16(aB + swz128(row, ch), g_Ahi + (size_t)(bm0 + row) * KP + kloc + ch * 8);
        }
#pragma unroll
        for (int j = 0; j < 4; j++) {
            int u = tid + j * 512;                 // B: 256 rows x 8 slots = 2048 units
            int row = u >> 3, ch = u & 7;
            cpasync16(bB + swz128(row, ch), g_Whi + (size_t)(bn0 + row) * KP + kloc + ch * 8);
        }
        asm volatile("cp.async.commit_group;");
    };

    load_stage(0, 0);
    load_stage(1, 1);

    const int rit = (lane & 7) + ((lane >> 3) & 1) * 8;
    const int kh = lane >> 4;

    for (int cidx = 0; cidx < NCHUNK; cidx++) {
        const int st = cidx & 3;
        if (cidx + 2 < NCHUNK) {
            load_stage(cidx + 2, (cidx + 2) & 3);
            asm volatile("cp.async.wait_group 2;");    // chunk c complete (own copies)
        } else if (cidx + 1 < NCHUNK) {
            asm volatile("cp.async.wait_group 1;");
        } else {
            asm volatile("cp.async.wait_group 0;");
        }
        __syncthreads();                               // cross-thread visibility of chunk c

        const uint32_t aB = sb + st * STAGE_B;
        const uint32_t bB = aB + A_BYTES;

        uint32_t a[2][2][4], b[2][4][4];
        {
            const int kch = kh;       // ks = 0
#pragma unroll
            for (int mi = 0; mi < 2; mi++)
                ldmatrix_x4(a[0][mi], aB + swz128(warp_m * 32 + mi * 16 + rit, kch));
#pragma unroll
            for (int nj = 0; nj < 4; nj++)
                ldmatrix_x4(b[0][nj], bB + swz128(warp_n * 64 + nj * 16 + rit, kch));
        }
#pragma unroll
        for (int ks = 0; ks < 4; ks++) {
            const int cur = ks & 1, nxt = cur ^ 1;
            if (ks < 3) {
                const int kch = (ks + 1) * 2 + kh;
#pragma unroll
                for (int mi = 0; mi < 2; mi++)
                    ldmatrix_x4(a[nxt][mi], aB + swz128(warp_m * 32 + mi * 16 + rit, kch));
#pragma unroll
                for (int nj = 0; nj < 4; nj++)
                    ldmatrix_x4(b[nxt][nj], bB + swz128(warp_n * 64 + nj * 16 + rit, kch));
            }
#pragma unroll
            for (int mi = 0; mi < 2; mi++)
#pragma unroll
                for (int nj = 0; nj < 4; nj++) {
                    mma_bf16(c[mi][2 * nj],     a[cur][mi], b[cur][nj][0], b[cur][nj][2]);
                    mma_bf16(c[mi][2 * nj + 1], a[cur][mi], b[cur][nj][1], b[cur][nj][3]);
                }
        }
    }

    // epilogue: convert fp32 acc -> bf16 pairs
#pragma unroll
    for (int mi = 0; mi < 2; mi++) {
        const int r0 = bm0 + warp_m * 32 + mi * 16 + (lane >> 2);
#pragma unroll
        for (int nj = 0; nj < 4; nj++) {
#pragma unroll
            for (int h = 0; h < 2; h++) {
                const float* cc = c[mi][2 * nj + h];
                const int col = bn0 + warp_n * 64 + nj * 16 + h * 8 + (lane & 3) * 2;
                __nv_bfloat162 p0 = __float22bfloat162_rn(make_float2(cc[0], cc[1]));
                __nv_bfloat162 p1 = __float22bfloat162_rn(make_float2(cc[2], cc[3]));
                *(__nv_bfloat162*)&g_P[(size_t)r0 * NCOLS + col]       = p0;
                *(__nv_bfloat162*)&g_P[(size_t)(r0 + 8) * NCOLS + col] = p1;
            }
        }
    }
}

// ================= K2: tap-combine + bias + ReLU + L2-normalize (bf16 in/out) =====
__global__ void k2_combine(const float* __restrict__ cb1,
                           const float* __restrict__ cb2,
                           const float* __restrict__ cb3)
{
    const int r = blockIdx.x;
    const int c = threadIdx.x;
    int l, L, rr;
    const bool isq = (r < QROWS);
    if (isq) { rr = r;          l = r % Q_;  L = Q_; }
    else     { rr = r - QROWS;  l = rr % D_; L = D_; }

    const __nv_bfloat16* Pr = g_P + (size_t)r * NCOLS;
    float v1 = cb1[c] + __bfloat162float(Pr[c]);
    float v2 = cb2[c] + __bfloat162float(Pr[128 + c]);
    float v3 = cb3[c] + __bfloat162float(Pr[384 + c]);
    if (l + 1 < L) {
        v2 += __bfloat162float(Pr[NCOLS + 256 + c]);
        v3 += __bfloat162float(Pr[NCOLS + 512 + c]);
    }
    if (l + 2 < L) v3 += __bfloat162float(Pr[2 * NCOLS + 640 + c]);
    v1 = fmaxf(v1, 0.f); v2 = fmaxf(v2, 0.f); v3 = fmaxf(v3, 0.f);

    float s1 = v1 * v1, s2 = v2 * v2, s3 = v3 * v3;
#pragma unroll
    for (int o = 16; o; o >>= 1) {
        s1 += __shfl_xor_sync(0xffffffffu, s1, o);
        s2 += __shfl_xor_sync(0xffffffffu, s2, o);
        s3 += __shfl_xor_sync(0xffffffffu, s3, o);
    }
    __shared__ float sred[3][4];
    const int lane = c & 31, w = c >> 5;
    if (lane == 0) { sred[0][w] = s1; sred[1][w] = s2; sred[2][w] = s3; }
    __syncthreads();
    float ss1 = sred[0][0] + sred[0][1] + sred[0][2] + sred[0][3];
    float ss2 = sred[1][0] + sred[1][1] + sred[1][2] + sred[1][3];
    float ss3 = sred[2][0] + sred[2][1] + sred[2][2] + sred[2][3];
    float n1 = v1 * (1.0f / (sqrtf(ss1) + 1e-13f));
    float n2 = v2 * (1.0f / (sqrtf(ss2) + 1e-13f));
    float n3 = v3 * (1.0f / (sqrtf(ss3) + 1e-13f));

    float nv[3] = {n1, n2, n3};
#pragma unroll
    for (int t = 0; t < 3; t++) {
        __nv_bfloat16 h = __float2bfloat16(nv[t]);
        __nv_bfloat16 lo = __float2bfloat16(nv[t] - __bfloat162float(h));
        if (isq) {
            size_t o = ((size_t)t * QROWS + rr) * C_ + c;
            g_qnh[o] = h; g_qnl[o] = lo;
        } else {
            size_t o = ((size_t)t * DROWS + rr) * C_ + c;
            g_dnh[o] = h; g_dnl[o] = lo;
        }
    }
}

// ================= K3: HMMA cosine GEMM + chain-RBF + log pooling =================
#define K3Q_HI   0
#define K3Q_LO   8192
#define K3D      16384
#define K3SPK    81920
#define K3QM     83328
#define K3DM     83456
#define K3_SMEM  84480

__global__ __launch_bounds__(512, 2) void k3h(const int* __restrict__ qtok,
                                              const int* __restrict__ dtok)
{
    extern __shared__ char smem[];
    const uint32_t sb = smem_u32(smem);
    float* spk = (float*)(smem + K3SPK);
    float* qm  = (float*)(smem + K3QM);
    float* dm  = (float*)(smem + K3DM);

    const int b = blockIdx.x, pair = blockIdx.y;
    const int qi3 = pair / 3, dj3 = pair % 3;
    const int tid = threadIdx.x, lane = tid & 31, wid = tid >> 5;
    const int mi = wid >> 3, wn = wid & 7;

    if (tid < 352) spk[tid] = 0.f;
    if (tid < 32) qm[tid] = (tid < Q_ && qtok[b * Q_ + tid] > 0) ? 1.f : 0.f;
    else if (tid < 288) { int d = tid - 32; dm[d] = (d < D_ && dtok[b * D_ + d] > 0) ? 1.f : 0.f; }

    const __nv_bfloat16* qh = g_qnh + ((size_t)qi3 * QROWS + b * Q_) * C_;
    const __nv_bfloat16* qlp = g_qnl + ((size_t)qi3 * QROWS + b * Q_) * C_;
    const __nv_bfloat16* dh = g_dnh + ((size_t)dj3 * DROWS + b * D_) * C_;
    const __nv_bfloat16* dl = g_dnl + ((size_t)dj3 * DROWS + b * D_) * C_;

    {
        int kc = tid >> 7, row = (tid >> 2) & 31, ch = tid & 3;
        int sz = (row < Q_) ? 16 : 0;
        int srow = (row < Q_) ? row : 0;
        size_t so = (size_t)srow * C_ + kc * 32 + ch * 8;
        uint32_t dst = sb + kc * 2048 + swz(row, ch);
        cpasync16z(dst,          qh  + so, sz);
        cpasync16z(dst + K3Q_LO, qlp + so, sz);
    }

    auto load_d = [&](int kc, int buf) {
#pragma unroll
        for (int j = 0; j < 2; j++) {
            int u = tid + j * 512;
            int row = u >> 2, ch = u & 3;
            int sz = (row < D_) ? 16 : 0;
            int srow = (row < D_) ? row : 0;
            size_t so = (size_t)srow * C_ + kc * 32 + ch * 8;
            uint32_t dst = sb + K3D + buf * 32768 + swz(row, ch);
            cpasync16z(dst,          dh + so, sz);
            cpasync16z(dst + 16384,  dl + so, sz);
        }
        asm volatile("cp.async.commit_group;");
    };

    load_d(0, 0);

    float c[4][4];
#pragma unroll
    for (int i = 0; i < 4; i++)
#pragma unroll
        for (int j = 0; j < 4; j++) c[i][j] = 0.f;

    const int rit = (lane & 7) + ((lane >> 3) & 1) * 8;

    for (int kc = 0; kc < 4; kc++) {
        if (kc < 3) load_d(kc + 1, (kc + 1) & 1);
        if (kc < 3) asm volatile("cp.async.wait_group 1;");
        else        asm volatile("cp.async.wait_group 0;");
        __syncthreads();
        const uint32_t dbB = sb + K3D + (kc & 1) * 32768;
#pragma unroll
        for (int pass = 0; pass < 3; pass++) {
            const uint32_t qB = sb + ((pass == 2) ? K3Q_LO : K3Q_HI) + kc * 2048;
            const uint32_t dB = dbB + ((pass == 1) ? 16384 : 0);
#pragma unroll
            for (int ks = 0; ks < 2; ks++) {
                int kch = ks * 2 + (lane >> 4);
                uint32_t a[4], b0[4], b1[4];
                ldmatrix_x4(a,  qB + swz(mi * 16 + rit, kch));
                ldmatrix_x4(b0, dB + swz(wn * 32 + rit, kch));
                ldmatrix_x4(b1, dB + swz(wn * 32 + 16 + rit, kch));
                mma_bf16(c[0], a, b0[0], b0[2]);
                mma_bf16(c[1], a, b0[1], b0[3]);
                mma_bf16(c[2], a, b1[0], b1[2]);
                mma_bf16(c[3], a, b1[1], b1[3]);
            }
        }
        __syncthreads();
    }

    const float K20 = 28.853901f;       //  20*log2(e)
    const float AW  = -72.134754f;      // -50*log2(e)
    const float A0  = -7.2134754e8f;    // -5e5*log2(e)
    const u64 C4  = dupf(1.8315639e-2f);
    const u64 C8  = dupf(3.3546262e-4f);
    const u64 C12 = dupf(6.1442124e-6f);
    const u64 C16 = dupf(1.1253517e-7f);

#pragma unroll
    for (int s = 0; s < 2; s++) {
        const int row = mi * 16 + (lane >> 2) + s * 8;
        const float qmr = qm[row];
        float pk0 = 0.f;
        u64 pk56 = 0, pk47 = 0, pk38 = 0, pk29 = 0, pk110 = 0;

        float cmv[8], mv[8];
        float maxc = 0.f;
#pragma unroll
        for (int nj = 0; nj < 4; nj++) {
#pragma unroll
            for (int h = 0; h < 2; h++) {
                int idx = nj * 2 + h;
                int col = wn * 32 + nj * 8 + (lane & 3) * 2 + h;
                float m = qmr * dm[col];
                float cm = c[nj][2 * s + h] * m;
                mv[idx] = m; cmv[idx] = cm;
                maxc = fmaxf(maxc, cm);
            }
        }

        // wide kernels: center-out packed chains (3 ex2 per element)
#pragma unroll
        for (int idx = 0; idx < 8; idx++) {
            float m = mv[idx], cm = cmv[idx];
            float arg = cm * K20;
            float t  = ex2f(arg);
            float ti = ex2f(-arg);
            u64 tt = packf(t, ti);
            float dlt = cm - 0.1f;
            float gl = ex2f(dlt * dlt * AW);
            u64 ab = packf(gl, gl * ti);
            u64 m2 = dupf(m);
            ffma2(pk56, m2, ab);
            ab = mul2(ab, tt); ab = mul2(ab, C4);  ffma2(pk47, m2, ab);
            ab = mul2(ab, tt); ab = mul2(ab, C8);  ffma2(pk38, m2, ab);
            ab = mul2(ab, tt); ab = mul2(ab, C12); ffma2(pk29, m2, ab);
            ab = mul2(ab, tt); ab = mul2(ab, C16); ffma2(pk110, m2, ab);
        }

        // exact-match kernel: skipped unless some lane has cm > 0.99
        if (__any_sync(0xffffffffu, maxc > 0.99f)) {
#pragma unroll
            for (int idx = 0; idx < 8; idx++) {
                float d1 = cmv[idx] - 1.f;
                pk0 = fmaf(mv[idx], ex2f(d1 * d1 * A0), pk0);
            }
        }

#pragma unroll
        for (int o = 1; o <= 2; o <<= 1) {
            pk0  += __shfl_xor_sync(0xffffffffu, pk0, o);
            pk56  = add2(pk56,  __shfl_xor_sync(0xffffffffu, pk56, o));
            pk47  = add2(pk47,  __shfl_xor_sync(0xffffffffu, pk47, o));
            pk38  = add2(pk38,  __shfl_xor_sync(0xffffffffu, pk38, o));
            pk29  = add2(pk29,  __shfl_xor_sync(0xffffffffu, pk29, o));
            pk110 = add2(pk110, __shfl_xor_sync(0xffffffffu, pk110, o));
        }
        if ((lane & 3) == 0) {
            float lo, hi;
            float* rw = spk + row * 11;
            atomicAdd(&rw[0], pk0);
            unpackf(pk56,  lo, hi); atomicAdd(&rw[5], lo); atomicAdd(&rw[6],  hi);
            unpackf(pk47,  lo, hi); atomicAdd(&rw[4], lo); atomicAdd(&rw[7],  hi);
            unpackf(pk38,  lo, hi); atomicAdd(&rw[3], lo); atomicAdd(&rw[8],  hi);
            unpackf(pk29,  lo, hi); atomicAdd(&rw[2], lo); atomicAdd(&rw[9],  hi);
            unpackf(pk110, lo, hi); atomicAdd(&rw[1], lo); atomicAdd(&rw[10], hi);
        }
    }
    __syncthreads();

    if (tid < 11) {
        float f = 0.f;
        for (int q = 0; q < Q_; q++)
            f += logf(fmaxf(spk[q * 11 + tid], 1e-10f)) * 0.01f * qm[q];
        g_feats[(b * 9 + pair) * 11 + tid] = f;
    }
}

// ================= K4: final dense =================
__global__ void k4_out(const float* __restrict__ dw, float* __restrict__ out)
{
    int b = threadIdx.x;
    float f = 0.f;
#pragma unroll
    for (int j = 0; j < 99; j++) f += g_feats[b * 99 + j] * dw[j];
    out[b] = f;
}

// ================= launch =================
extern "C" void kernel_launch(void* const* d_in, const int* in_sizes, int n_in,
                              void* d_out, int out_size)
{
    (void)in_sizes; (void)n_in; (void)out_size;
    const int*   qtok = (const int*)d_in[0];
    const int*   dtok = (const int*)d_in[1];
    const float* emb  = (const float*)d_in[2];
    const float* w1   = (const float*)d_in[3];
    const float* w2   = (const float*)d_in[4];
    const float* w3   = (const float*)d_in[5];
    const float* cb1  = (const float*)d_in[6];
    const float* cb2  = (const float*)d_in[7];
    const float* cb3  = (const float*)d_in[8];
    const float* dw   = (const float*)d_in[9];
    float* out = (float*)d_out;

    cudaFuncSetAttribute(k1h, cudaFuncAttributeMaxDynamicSharedMemorySize, K1_SMEM);
    cudaFuncSetAttribute(k3h, cudaFuncAttributeMaxDynamicSharedMemorySize, K3_SMEM);

    pack_all<<<WBLOCKS + ABLOCKS, 256>>>(w1, w2, w3, emb, qtok, dtok);
    k1h<<<dim3(230, 3), 512, K1_SMEM>>>();
    k2_combine<<<NROWS, 128>>>(cb1, cb2, cb3);
    k3h<<<dim3(128, 9), 512, K3_SMEM>>>(qtok, dtok);
    k4_out<<<1, 128>>>(dw, out);
}

// round 16
// speedup vs baseline: 2.0702x; 1.1039x over previous
#include <cuda_runtime.h>
#include <cuda_fp16.h>
#include <cstdint>

// Problem constants
#define B_    128
#define Q_    30
#define D_    200
#define E_    300
#define C_    128
#define QROWS 3840
#define DROWS 25600
#define NROWS 29440          // 230 * 128
#define NCOLS 768
#define KP    320            // padded K

typedef unsigned long long u64;

// ================= f32x2 / misc helpers =================
__device__ __forceinline__ u64 dupf(float x) {
    u64 r; unsigned xi = __float_as_uint(x);
    asm("mov.b64 %0, {%1, %1};" : "=l"(r) : "r"(xi));
    return r;
}
__device__ __forceinline__ u64 packf(float lo, float hi) {
    u64 r; unsigned a = __float_as_uint(lo), b = __float_as_uint(hi);
    asm("mov.b64 %0, {%1, %2};" : "=l"(r) : "r"(a), "r"(b));
    return r;
}
__device__ __forceinline__ void unpackf(u64 v, float& lo, float& hi) {
    unsigned a, b;
    asm("mov.b64 {%0, %1}, %2;" : "=r"(a), "=r"(b) : "l"(v));
    lo = __uint_as_float(a); hi = __uint_as_float(b);
}
__device__ __forceinline__ void ffma2(u64& d, u64 a, u64 b) {
    asm("fma.rn.f32x2 %0, %1, %2, %0;" : "+l"(d) : "l"(a), "l"(b));
}
__device__ __forceinline__ u64 add2(u64 a, u64 b) {
    u64 r; asm("add.rn.f32x2 %0, %1, %2;" : "=l"(r) : "l"(a), "l"(b)); return r;
}
__device__ __forceinline__ u64 mul2(u64 a, u64 b) {
    u64 r; asm("mul.rn.f32x2 %0, %1, %2;" : "=l"(r) : "l"(a), "l"(b)); return r;
}
__device__ __forceinline__ float ex2f(float x) {
    float r; asm("ex2.approx.f32 %0, %1;" : "=f"(r) : "f"(x)); return r;
}
__device__ __forceinline__ void cpasync16(uint32_t sdst, const void* gsrc) {
    asm volatile("cp.async.cg.shared.global [%0], [%1], 16;" :: "r"(sdst), "l"(gsrc));
}
__device__ __forceinline__ void cpasync16z(uint32_t sdst, const void* gsrc, int sz) {
    asm volatile("cp.async.cg.shared.global [%0], [%1], 16, %2;" :: "r"(sdst), "l"(gsrc), "r"(sz));
}
__device__ __forceinline__ uint32_t smem_u32(const void* p) {
    uint32_t a;
    asm("{ .reg .u64 t; cvta.to.shared.u64 t, %1; cvt.u32.u64 %0, t; }" : "=r"(a) : "l"(p));
    return a;
}
__device__ __forceinline__ void ldmatrix_x4(uint32_t* r, uint32_t saddr) {
    asm volatile("ldmatrix.sync.aligned.m8n8.x4.shared.b16 {%0,%1,%2,%3}, [%4];"
                 : "=r"(r[0]), "=r"(r[1]), "=r"(r[2]), "=r"(r[3]) : "r"(saddr));
}
__device__ __forceinline__ void mma_f16(float* c, const uint32_t* a,
                                        uint32_t b0, uint32_t b1) {
    asm volatile("mma.sync.aligned.m16n8k16.row.col.f32.f16.f16.f32 "
                 "{%0,%1,%2,%3}, {%4,%5,%6,%7}, {%8,%9}, {%0,%1,%2,%3};"
                 : "+f"(c[0]), "+f"(c[1]), "+f"(c[2]), "+f"(c[3])
                 : "r"(a[0]), "r"(a[1]), "r"(a[2]), "r"(a[3]), "r"(b0), "r"(b1));
}

// ================= device scratch (fp16 pipeline) =================
__device__ __half g_Ah[(size_t)NROWS * KP];
__device__ __half g_Wh[(size_t)NCOLS * KP];
__device__ __half g_P[(size_t)NROWS * NCOLS];
__device__ __half g_qn[3 * (size_t)QROWS * C_];
__device__ __half g_dn[3 * (size_t)DROWS * C_];
__device__ float g_feats[B_ * 99];

// ================= pack kernel (W + A merged) =================
#define WBLOCKS ((NCOLS * KP + 255) / 256)
#define ABLOCKS ((NROWS * (KP / 4) + 255) / 256)
__global__ void pack_all(const float* __restrict__ w1,
                         const float* __restrict__ w2,
                         const float* __restrict__ w3,
                         const float* __restrict__ emb,
                         const int* __restrict__ qtok,
                         const int* __restrict__ dtok)
{
    if (blockIdx.x < WBLOCKS) {
        int idx = blockIdx.x * 256 + threadIdx.x;
        if (idx >= NCOLS * KP) return;
        int n = idx / KP, k = idx % KP;
        float v = 0.f;
        if (k < E_) {
            if (n < 128)       v = w1[n * E_ + k];
            else if (n < 384) { int u = n - 128; v = w2[(u & 127) * (E_ * 2) + k * 2 + (u >> 7)]; }
            else              { int u = n - 384; v = w3[(u & 127) * (E_ * 3) + k * 3 + (u >> 7)]; }
        }
        g_Wh[idx] = __float2half(v);
    } else {
        int idx = (blockIdx.x - WBLOCKS) * 256 + threadIdx.x;
        if (idx >= NROWS * (KP / 4)) return;
        int r = idx / (KP / 4), g = idx % (KP / 4);
        int k = g * 4;
        float4 v = make_float4(0.f, 0.f, 0.f, 0.f);
        if (k < E_) {
            int tok = (r < QROWS) ? qtok[r] : dtok[r - QROWS];
            v = *(const float4*)(emb + (size_t)tok * E_ + k);
        }
        float vv[4] = {v.x, v.y, v.z, v.w};
        u64 hw = 0;
#pragma unroll
        for (int i = 0; i < 4; i++) {
            __half h = __float2half(vv[i]);
            hw |= (u64)(*(unsigned short*)&h) << (16 * i);
        }
        *(u64*)(g_Ah + (size_t)r * KP + k) = hw;
    }
}

// ================= K1: HMMA GEMM  P = A @ W^T  (fp16 single pass, K=320) =====
// CTA tile 128x256, 16 warps (4x4), warp tile 32x64, KC=64, 4-stage cp.async ring.
#define KC        64
#define NCHUNK    5
#define A_BYTES   (128 * 128)      // 128 rows * 128B (64 fp16)
#define B_BYTES   (256 * 128)
#define STAGE_B   (A_BYTES + B_BYTES)
#define K1_SMEM   (4 * STAGE_B)    // 196608

// full SW128 swizzle: 128B rows, 8 x 16B slots, slot ^= (row & 7)
__device__ __forceinline__ uint32_t swz128(int row, int ch) {
    return (uint32_t)(row * 128 + ((ch ^ (row & 7)) << 4));
}
// 64B-row swizzle for k3h tiles
__device__ __forceinline__ uint32_t swz(int row, int ch) {
    return (uint32_t)(row * 64 + ((ch ^ ((row >> 1) & 3)) << 4));
}

__global__ __launch_bounds__(512, 1) void k1h()
{
    extern __shared__ char smem[];
    const uint32_t sb = smem_u32(smem);
    const int tid = threadIdx.x;
    const int lane = tid & 31;
    const int wid = tid >> 5;
    const int warp_m = wid & 3;        // 0..3 (32 rows each)
    const int warp_n = wid >> 2;       // 0..3 (64 cols each)
    const int bm0 = blockIdx.x * 128;
    const int bn0 = blockIdx.y * 256;

    float c[2][8][4];
#pragma unroll
    for (int i = 0; i < 2; i++)
#pragma unroll
        for (int j = 0; j < 8; j++)
#pragma unroll
            for (int k = 0; k < 4; k++) c[i][j][k] = 0.f;

    auto load_stage = [&](int chunk, int st) {
        const int kloc = chunk * KC;
        const uint32_t aB = sb + st * STAGE_B;
        const uint32_t bB = aB + A_BYTES;
#pragma unroll
        for (int j = 0; j < 2; j++) {
            int u = tid + j * 512;                 // A: 128 rows x 8 slots = 1024 units
            int row = u >> 3, ch = u & 7;
            cpasync16(aB + swz128(row, ch), g_Ah + (size_t)(bm0 + row) * KP + kloc + ch * 8);
        }
#pragma unroll
        for (int j = 0; j < 4; j++) {
            int u = tid + j * 512;                 // B: 256 rows x 8 slots = 2048 units
            int row = u >> 3, ch = u & 7;
            cpasync16(bB + swz128(row, ch), g_Wh + (size_t)(bn0 + row) * KP + kloc + ch * 8);
        }
        asm volatile("cp.async.commit_group;");
    };

    load_stage(0, 0);
    load_stage(1, 1);

    const int rit = (lane & 7) + ((lane >> 3) & 1) * 8;
    const int kh = lane >> 4;

    for (int cidx = 0; cidx < NCHUNK; cidx++) {
        const int st = cidx & 3;
        if (cidx + 2 < NCHUNK) {
            load_stage(cidx + 2, (cidx + 2) & 3);
            asm volatile("cp.async.wait_group 2;");
        } else if (cidx + 1 < NCHUNK) {
            asm volatile("cp.async.wait_group 1;");
        } else {
            asm volatile("cp.async.wait_group 0;");
        }
        __syncthreads();

        const uint32_t aB = sb + st * STAGE_B;
        const uint32_t bB = aB + A_BYTES;

        uint32_t a[2][2][4], b[2][4][4];
        {
            const int kch = kh;       // ks = 0
#pragma unroll
            for (int mi = 0; mi < 2; mi++)
                ldmatrix_x4(a[0][mi], aB + swz128(warp_m * 32 + mi * 16 + rit, kch));
#pragma unroll
            for (int nj = 0; nj < 4; nj++)
                ldmatrix_x4(b[0][nj], bB + swz128(warp_n * 64 + nj * 16 + rit, kch));
        }
#pragma unroll
        for (int ks = 0; ks < 4; ks++) {
            const int cur = ks & 1, nxt = cur ^ 1;
            if (ks < 3) {
                const int kch = (ks + 1) * 2 + kh;
#pragma unroll
                for (int mi = 0; mi < 2; mi++)
                    ldmatrix_x4(a[nxt][mi], aB + swz128(warp_m * 32 + mi * 16 + rit, kch));
#pragma unroll
                for (int nj = 0; nj < 4; nj++)
                    ldmatrix_x4(b[nxt][nj], bB + swz128(warp_n * 64 + nj * 16 + rit, kch));
            }
#pragma unroll
            for (int mi = 0; mi < 2; mi++)
#pragma unroll
                for (int nj = 0; nj < 4; nj++) {
                    mma_f16(c[mi][2 * nj],     a[cur][mi], b[cur][nj][0], b[cur][nj][2]);
                    mma_f16(c[mi][2 * nj + 1], a[cur][mi], b[cur][nj][1], b[cur][nj][3]);
                }
        }
    }

    // epilogue: convert fp32 acc -> fp16 pairs
#pragma unroll
    for (int mi = 0; mi < 2; mi++) {
        const int r0 = bm0 + warp_m * 32 + mi * 16 + (lane >> 2);
#pragma unroll
        for (int nj = 0; nj < 4; nj++) {
#pragma unroll
            for (int h = 0; h < 2; h++) {
                const float* cc = c[mi][2 * nj + h];
                const int col = bn0 + warp_n * 64 + nj * 16 + h * 8 + (lane & 3) * 2;
                __half2 p0 = __floats2half2_rn(cc[0], cc[1]);
                __half2 p1 = __floats2half2_rn(cc[2], cc[3]);
                *(__half2*)&g_P[(size_t)r0 * NCOLS + col]       = p0;
                *(__half2*)&g_P[(size_t)(r0 + 8) * NCOLS + col] = p1;
            }
        }
    }
}

// ================= K2: tap-combine + bias + ReLU + L2-normalize (fp16 in/out) =====
__global__ void k2_combine(const float* __restrict__ cb1,
                           const float* __restrict__ cb2,
                           const float* __restrict__ cb3)
{
    const int r = blockIdx.x;
    const int c = threadIdx.x;
    int l, L, rr;
    const bool isq = (r < QROWS);
    if (isq) { rr = r;          l = r % Q_;  L = Q_; }
    else     { rr = r - QROWS;  l = rr % D_; L = D_; }

    const __half* Pr = g_P + (size_t)r * NCOLS;
    float v1 = cb1[c] + __half2float(Pr[c]);
    float v2 = cb2[c] + __half2float(Pr[128 + c]);
    float v3 = cb3[c] + __half2float(Pr[384 + c]);
    if (l + 1 < L) {
        v2 += __half2float(Pr[NCOLS + 256 + c]);
        v3 += __half2float(Pr[NCOLS + 512 + c]);
    }
    if (l + 2 < L) v3 += __half2float(Pr[2 * NCOLS + 640 + c]);
    v1 = fmaxf(v1, 0.f); v2 = fmaxf(v2, 0.f); v3 = fmaxf(v3, 0.f);

    float s1 = v1 * v1, s2 = v2 * v2, s3 = v3 * v3;
#pragma unroll
    for (int o = 16; o; o >>= 1) {
        s1 += __shfl_xor_sync(0xffffffffu, s1, o);
        s2 += __shfl_xor_sync(0xffffffffu, s2, o);
        s3 += __shfl_xor_sync(0xffffffffu, s3, o);
    }
    __shared__ float sred[3][4];
    const int lane = c & 31, w = c >> 5;
    if (lane == 0) { sred[0][w] = s1; sred[1][w] = s2; sred[2][w] = s3; }
    __syncthreads();
    float ss1 = sred[0][0] + sred[0][1] + sred[0][2] + sred[0][3];
    float ss2 = sred[1][0] + sred[1][1] + sred[1][2] + sred[1][3];
    float ss3 = sred[2][0] + sred[2][1] + sred[2][2] + sred[2][3];
    float n1 = v1 * (1.0f / (sqrtf(ss1) + 1e-13f));
    float n2 = v2 * (1.0f / (sqrtf(ss2) + 1e-13f));
    float n3 = v3 * (1.0f / (sqrtf(ss3) + 1e-13f));

    float nv[3] = {n1, n2, n3};
#pragma unroll
    for (int t = 0; t < 3; t++) {
        __half h = __float2half(nv[t]);
        if (isq) g_qn[((size_t)t * QROWS + rr) * C_ + c] = h;
        else     g_dn[((size_t)t * DROWS + rr) * C_ + c] = h;
    }
}

// ================= K3: fp16 HMMA cosine GEMM + chain-RBF + log pooling =================
// smem: q 4kc x 2KB = 8192 | d 2 bufs x 16384 | spk 1408 | qm 128 | dm 1024
#define K3Q      0
#define K3D      8192
#define K3SPK    40960
#define K3QM     42368
#define K3DM     42496
#define K3_SMEM  43520

__global__ __launch_bounds__(512, 2) void k3h(const int* __restrict__ qtok,
                                              const int* __restrict__ dtok)
{
    extern __shared__ char smem[];
    const uint32_t sb = smem_u32(smem);
    float* spk = (float*)(smem + K3SPK);
    float* qm  = (float*)(smem + K3QM);
    float* dm  = (float*)(smem + K3DM);

    const int b = blockIdx.x, pair = blockIdx.y;
    const int qi3 = pair / 3, dj3 = pair % 3;
    const int tid = threadIdx.x, lane = tid & 31, wid = tid >> 5;
    const int mi = wid >> 3, wn = wid & 7;

    if (tid < 352) spk[tid] = 0.f;
    if (tid < 32) qm[tid] = (tid < Q_ && qtok[b * Q_ + tid] > 0) ? 1.f : 0.f;
    else if (tid < 288) { int d = tid - 32; dm[d] = (d < D_ && dtok[b * D_ + d] > 0) ? 1.f : 0.f; }

    const __half* qh = g_qn + ((size_t)qi3 * QROWS + b * Q_) * C_;
    const __half* dh = g_dn + ((size_t)dj3 * DROWS + b * D_) * C_;

    // q loads: 512 units = [4 kc][32 row][4 ch]
    {
        int kc = tid >> 7, row = (tid >> 2) & 31, ch = tid & 3;
        int sz = (row < Q_) ? 16 : 0;
        int srow = (row < Q_) ? row : 0;
        cpasync16z(sb + K3Q + kc * 2048 + swz(row, ch),
                   qh + (size_t)srow * C_ + kc * 32 + ch * 8, sz);
    }

    auto load_d = [&](int kc, int buf) {
#pragma unroll
        for (int j = 0; j < 2; j++) {
            int u = tid + j * 512;                 // 256 rows x 4 ch = 1024 units
            int row = u >> 2, ch = u & 3;
            int sz = (row < D_) ? 16 : 0;
            int srow = (row < D_) ? row : 0;
            cpasync16z(sb + K3D + buf * 16384 + swz(row, ch),
                       dh + (size_t)srow * C_ + kc * 32 + ch * 8, sz);
        }
        asm volatile("cp.async.commit_group;");
    };

    load_d(0, 0);

    float c[4][4];
#pragma unroll
    for (int i = 0; i < 4; i++)
#pragma unroll
        for (int j = 0; j < 4; j++) c[i][j] = 0.f;

    const int rit = (lane & 7) + ((lane >> 3) & 1) * 8;

    for (int kc = 0; kc < 4; kc++) {
        if (kc < 3) load_d(kc + 1, (kc + 1) & 1);
        if (kc < 3) asm volatile("cp.async.wait_group 1;");
        else        asm volatile("cp.async.wait_group 0;");
        __syncthreads();
        if (wn != 7) {                         // cols 224..255 are zero padding: skip
            const uint32_t qB = sb + K3Q + kc * 2048;
            const uint32_t dB = sb + K3D + (kc & 1) * 16384;
#pragma unroll
            for (int ks = 0; ks < 2; ks++) {
                int kch = ks * 2 + (lane >> 4);
                uint32_t a[4], b0[4], b1[4];
                ldmatrix_x4(a,  qB + swz(mi * 16 + rit, kch));
                ldmatrix_x4(b0, dB + swz(wn * 32 + rit, kch));
                ldmatrix_x4(b1, dB + swz(wn * 32 + 16 + rit, kch));
                mma_f16(c[0], a, b0[0], b0[2]);
                mma_f16(c[1], a, b0[1], b0[3]);
                mma_f16(c[2], a, b1[0], b1[2]);
                mma_f16(c[3], a, b1[1], b1[3]);
            }
        }
        __syncthreads();
    }

    const float K20 = 28.853901f;       //  20*log2(e)
    const float AW  = -72.134754f;      // -50*log2(e)
    const float A0  = -7.2134754e8f;    // -5e5*log2(e)
    const u64 C4  = dupf(1.8315639e-2f);
    const u64 C8  = dupf(3.3546262e-4f);
    const u64 C12 = dupf(6.1442124e-6f);
    const u64 C16 = dupf(1.1253517e-7f);

    if (wn != 7) {
#pragma unroll
        for (int s = 0; s < 2; s++) {
            const int row = mi * 16 + (lane >> 2) + s * 8;
            const float qmr = qm[row];
            float pk0 = 0.f;
            u64 pk56 = 0, pk47 = 0, pk38 = 0, pk29 = 0, pk110 = 0;

            float cmv[8], mv[8];
            float maxc = 0.f;
#pragma unroll
            for (int nj = 0; nj < 4; nj++) {
#pragma unroll
                for (int h = 0; h < 2; h++) {
                    int idx = nj * 2 + h;
                    int col = wn * 32 + nj * 8 + (lane & 3) * 2 + h;
                    float m = qmr * dm[col];
                    float cm = c[nj][2 * s + h] * m;
                    mv[idx] = m; cmv[idx] = cm;
                    maxc = fmaxf(maxc, cm);
                }
            }

            // wide kernels: center-out packed chains (3 ex2 per element)
#pragma unroll
            for (int idx = 0; idx < 8; idx++) {
                float m = mv[idx], cm = cmv[idx];
                float arg = cm * K20;
                float t  = ex2f(arg);
                float ti = ex2f(-arg);
                u64 tt = packf(t, ti);
                float dlt = cm - 0.1f;
                float gl = ex2f(dlt * dlt * AW);
                u64 ab = packf(gl, gl * ti);
                u64 m2 = dupf(m);
                ffma2(pk56, m2, ab);
                ab = mul2(ab, tt); ab = mul2(ab, C4);  ffma2(pk47, m2, ab);
                ab = mul2(ab, tt); ab = mul2(ab, C8);  ffma2(pk38, m2, ab);
                ab = mul2(ab, tt); ab = mul2(ab, C12); ffma2(pk29, m2, ab);
                ab = mul2(ab, tt); ab = mul2(ab, C16); ffma2(pk110, m2, ab);
            }

            // exact-match kernel: skipped unless some lane has cm > 0.99
            // (skipped terms < e^-50; sums clipped at 1e-10 before log — harmless)
            if (__any_sync(0xffffffffu, maxc > 0.99f)) {
#pragma unroll
                for (int idx = 0; idx < 8; idx++) {
                    float d1 = cmv[idx] - 1.f;
                    pk0 = fmaf(mv[idx], ex2f(d1 * d1 * A0), pk0);
                }
            }

#pragma unroll
            for (int o = 1; o <= 2; o <<= 1) {
                pk0  += __shfl_xor_sync(0xffffffffu, pk0, o);
                pk56  = add2(pk56,  __shfl_xor_sync(0xffffffffu, pk56, o));
                pk47  = add2(pk47,  __shfl_xor_sync(0xffffffffu, pk47, o));
                pk38  = add2(pk38,  __shfl_xor_sync(0xffffffffu, pk38, o));
                pk29  = add2(pk29,  __shfl_xor_sync(0xffffffffu, pk29, o));
                pk110 = add2(pk110, __shfl_xor_sync(0xffffffffu, pk110, o));
            }
            if ((lane & 3) == 0) {
                float lo, hi;
                float* rw = spk + row * 11;
                atomicAdd(&rw[0], pk0);
                unpackf(pk56,  lo, hi); atomicAdd(&rw[5], lo); atomicAdd(&rw[6],  hi);
                unpackf(pk47,  lo, hi); atomicAdd(&rw[4], lo); atomicAdd(&rw[7],  hi);
                unpackf(pk38,  lo, hi); atomicAdd(&rw[3], lo); atomicAdd(&rw[8],  hi);
                unpackf(pk29,  lo, hi); atomicAdd(&rw[2], lo); atomicAdd(&rw[9],  hi);
                unpackf(pk110, lo, hi); atomicAdd(&rw[1], lo); atomicAdd(&rw[10], hi);
            }
        }
    }
    __syncthreads();

    if (tid < 11) {
        float f = 0.f;
        for (int q = 0; q < Q_; q++)
            f += logf(fmaxf(spk[q * 11 + tid], 1e-10f)) * 0.01f * qm[q];
        g_feats[(b * 9 + pair) * 11 + tid] = f;
    }
}

// ================= K4: final dense =================
__global__ void k4_out(const float* __restrict__ dw, float* __restrict__ out)
{
    int b = threadIdx.x;
    float f = 0.f;
#pragma unroll
    for (int j = 0; j < 99; j++) f += g_feats[b * 99 + j] * dw[j];
    out[b] = f;
}

// ================= launch =================
extern "C" void kernel_launch(void* const* d_in, const int* in_sizes, int n_in,
                              void* d_out, int out_size)
{
    (void)in_sizes; (void)n_in; (void)out_size;
    const int*   qtok = (const int*)d_in[0];
    const int*   dtok = (const int*)d_in[1];
    const float* emb  = (const float*)d_in[2];
    const float* w1   = (const float*)d_in[3];
    const float* w2   = (const float*)d_in[4];
    const float* w3   = (const float*)d_in[5];
    const float* cb1  = (const float*)d_in[6];
    const float* cb2  = (const float*)d_in[7];
    const float* cb3  = (const float*)d_in[8];
    const float* dw   = (const float*)d_in[9];
    float* out = (float*)d_out;

    cudaFuncSetAttribute(k1h, cudaFuncAttributeMaxDynamicSharedMemorySize, K1_SMEM);
    cudaFuncSetAttribute(k3h, cudaFuncAttributeMaxDynamicSharedMemorySize, K3_SMEM);

    pack_all<<<WBLOCKS + ABLOCKS, 256>>>(w1, w2, w3, emb, qtok, dtok);
    k1h<<<dim3(230, 3), 512, K1_SMEM>>>();
    k2_combine<<<NROWS, 128>>>(cb1, cb2, cb3);
    k3h<<<dim3(128, 9), 512, K3_SMEM>>>(qtok, dtok);
    k4_out<<<1, 128>>>(dw, out);
}